// round 13
// baseline (speedup 1.0000x reference)
#include <cuda_runtime.h>
#include <cuda_bf16.h>
#include <cuda_fp16.h>
#include <cstdint>
#include <cstddef>

// ---------------- static problem sizes -------------------------------------
#define SS      4
#define NH      4
#define CDIM    96
#define HD      24
#define NWIN    4096
#define TOKENS  262144
#define C3      288
#define CH      384

typedef __nv_bfloat16 bf16;

// ---------------- scratch ---------------------------------------------------
__device__ bf16  g_qkv[(size_t)TOKENS * C3];
__device__ bf16  g_o  [(size_t)TOKENS * CDIM];
__device__ float g_x1 [(size_t)TOKENS * CDIM];
__device__ bf16  g_h2 [(size_t)TOKENS * CDIM];
__device__ bf16  g_fc1[(size_t)TOKENS * CH];
__device__ bf16  g_wqkv[C3 * CDIM];
__device__ bf16  g_wproj[CDIM * CDIM];
__device__ bf16  g_wfc1[CH * CDIM];
__device__ bf16  g_wfc2[CDIM * CH];
__device__ float g_bias_exp[4 * 16384];   // per window-class bias+mask, x log2e

// ---------------- asm helpers ----------------------------------------------
__device__ __forceinline__ uint32_t smem_u32(const void* p) {
    return (uint32_t)__cvta_generic_to_shared(p);
}
__device__ __forceinline__ void ldm_x4(uint32_t& r0, uint32_t& r1, uint32_t& r2,
                                       uint32_t& r3, uint32_t addr) {
    asm volatile("ldmatrix.sync.aligned.m8n8.x4.shared.b16 {%0,%1,%2,%3}, [%4];\n"
                 : "=r"(r0), "=r"(r1), "=r"(r2), "=r"(r3) : "r"(addr));
}
__device__ __forceinline__ void mma_bf16(float c[4], const uint32_t a[4],
                                         const uint32_t b[2]) {
    asm volatile(
        "mma.sync.aligned.m16n8k16.row.col.f32.bf16.bf16.f32 "
        "{%0,%1,%2,%3},{%4,%5,%6,%7},{%8,%9},{%0,%1,%2,%3};\n"
        : "+f"(c[0]), "+f"(c[1]), "+f"(c[2]), "+f"(c[3])
        : "r"(a[0]), "r"(a[1]), "r"(a[2]), "r"(a[3]), "r"(b[0]), "r"(b[1]));
}
__device__ __forceinline__ void mma_f16(float c[4], const uint32_t a[4],
                                        const uint32_t b[2]) {
    asm volatile(
        "mma.sync.aligned.m16n8k16.row.col.f32.f16.f16.f32 "
        "{%0,%1,%2,%3},{%4,%5,%6,%7},{%8,%9},{%0,%1,%2,%3};\n"
        : "+f"(c[0]), "+f"(c[1]), "+f"(c[2]), "+f"(c[3])
        : "r"(a[0]), "r"(a[1]), "r"(a[2]), "r"(a[3]), "r"(b[0]), "r"(b[1]));
}
__device__ __forceinline__ void cp16(uint32_t dst, const void* src) {
    asm volatile("cp.async.ca.shared.global [%0], [%1], 16;\n"
                 :: "r"(dst), "l"(src));
}
__device__ __forceinline__ void cp_commit() { asm volatile("cp.async.commit_group;\n"); }
__device__ __forceinline__ void cp_wait0() { asm volatile("cp.async.wait_group 0;\n"); }
__device__ __forceinline__ void cp_wait1() { asm volatile("cp.async.wait_group 1;\n"); }

__device__ __forceinline__ float exp2_poly(float z) {
    z = fmaxf(z, -100.0f);
    float t = z + 12582912.0f;
    int   n = __float_as_int(t) - 0x4B400000;
    float f = z - (t - 12582912.0f);
    float p = 0.009618129107f;
    p = p * f + 0.05550410866f;
    p = p * f + 0.2402265069f;
    p = p * f + 0.69314718056f;
    p = p * f + 1.0f;
    return p * __int_as_float((n + 127) << 23);
}

// ---------------- weight conversion -----------------------------------------
__global__ void conv_weights(const float* __restrict__ a, const float* __restrict__ b,
                             const float* __restrict__ c, const float* __restrict__ d)
{
    int i = blockIdx.x * 256 + threadIdx.x;
    if (i < C3 * CDIM)   g_wqkv[i]  = __float2bfloat16(a[i]);
    if (i < CDIM * CDIM) g_wproj[i] = __float2bfloat16(b[i]);
    if (i < CH * CDIM) { g_wfc1[i]  = __float2bfloat16(c[i]);
                         g_wfc2[i]  = __float2bfloat16(d[i]); }
}

// ---------------- bias+mask expansion (4 window classes) --------------------
__global__ void build_bias(const float* __restrict__ rpb)
{
    int idx = blockIdx.x * 256 + threadIdx.x;     // 0..65535
    int cls = idx >> 14;
    int e   = idx & 16383;
    int q    = e & 3;
    int lane = (e >> 2) & 31;
    int nt   = (e >> 7) & 7;
    int mt   = (e >> 10) & 1;
    int mh   = (e >> 11) & 1;
    int head = (e >> 12) & 3;
    int gid = lane >> 2, tig = lane & 3;
    int n = mh*32 + mt*16 + gid + ((q >> 1) << 3);
    int m = nt*8 + tig*2 + (q & 1);
    int ni = n >> 3, nj = n & 7, mi = m >> 3, mj = m & 7;
    int ridx = (ni - mi + 7) * 15 + (nj - mj + 7);
    int wi7 = cls >> 1, wj7 = cls & 1;
    int rq = (wi7 ? ((ni < 4) ? 1 : 2) : 0) * 3 + (wj7 ? ((nj < 4) ? 1 : 2) : 0);
    int rk = (wi7 ? ((mi < 4) ? 1 : 2) : 0) * 3 + (wj7 ? ((mj < 4) ? 1 : 2) : 0);
    float mask = (rq != rk) ? -144.269504089f : 0.0f;
    g_bias_exp[idx] = rpb[ridx * NH + head] * 1.4426950408889634f + mask;
}

// ---------------- vectorized LN row helper ----------------------------------
__device__ __forceinline__ void ln_row_v4(const float* __restrict__ xr,
                                          const float* __restrict__ g,
                                          const float* __restrict__ b,
                                          bf16* __restrict__ orow, int lane)
{
    float4 v = make_float4(0.f, 0.f, 0.f, 0.f);
    if (lane < 24) v = *(const float4*)(xr + lane * 4);
    float s  = v.x + v.y + v.z + v.w;
    float ss = v.x*v.x + v.y*v.y + v.z*v.z + v.w*v.w;
    #pragma unroll
    for (int o = 16; o; o >>= 1) {
        s  += __shfl_xor_sync(0xffffffffu, s,  o);
        ss += __shfl_xor_sync(0xffffffffu, ss, o);
    }
    float mu = s * (1.0f/CDIM);
    float rs = rsqrtf(ss * (1.0f/CDIM) - mu*mu + 1e-5f);
    if (lane < 24) {
        float4 gv = *(const float4*)(g + lane * 4);
        float4 bv = *(const float4*)(b + lane * 4);
        __nv_bfloat162 lo((__nv_bfloat16)((v.x - mu) * rs * gv.x + bv.x),
                          (__nv_bfloat16)((v.y - mu) * rs * gv.y + bv.y));
        __nv_bfloat162 hi((__nv_bfloat16)((v.z - mu) * rs * gv.z + bv.z),
                          (__nv_bfloat16)((v.w - mu) * rs * gv.w + bv.w));
        uint2 pk;
        pk.x = *(uint32_t*)&lo;
        pk.y = *(uint32_t*)&hi;
        *(uint2*)(orow + lane * 4) = pk;
    }
}

// ---------------- N-loop GEMM (A resident full-K, B streamed per N-chunk) ---
#define AROW 104
#define NLOOP_SMEM (128*AROW*2 + 2*96*AROW*2)

template<int MODE, int NC>
__global__ void __launch_bounds__(256, 3)
gemm_nloop(const void* __restrict__ Ain, const bf16* __restrict__ W,
           const float* __restrict__ bias,
           const float* __restrict__ g1, const float* __restrict__ b1,
           bf16* __restrict__ Cout, int N)
{
    extern __shared__ __align__(16) char dyn[];
    bf16* As = (bf16*)dyn;
    bf16* Bs = (bf16*)(dyn + 128*AROW*2);

    const int t = threadIdx.x, warp = t >> 5, lane = t & 31;
    const int bm = blockIdx.x * 128;
    const int wrow = warp & 3, wcol = warp >> 2;
    const int gid = lane >> 2, tig = lane & 3;

    auto issueB = [&](int nc, int buf) {
        const bf16* Wb = W + (size_t)(nc * 96) * CDIM;
        bf16* Bd = Bs + buf * 96 * AROW;
        #pragma unroll
        for (int cid = t; cid < 1152; cid += 256) {
            int row = cid / 12, c = cid % 12;
            cp16(smem_u32(Bd + row * AROW + c * 8),
                 Wb + (size_t)row * CDIM + c * 8);
        }
        cp_commit();
    };

    issueB(0, 0);

    if (MODE == 0) {
        const float* x = (const float*)Ain;
        #pragma unroll
        for (int it = 0; it < 16; it++) {
            int r  = it * 8 + warp;
            int wr = bm + r;
            int w = (wr >> 6) & 63, s = wr & 63;
            int i0 = ((w >> 3) << 3) + (s >> 3), j0 = ((w & 7) << 3) + (s & 7);
            int src = (wr & ~4095) | ((((i0 + SS) & 63) << 6) | ((j0 + SS) & 63));
            ln_row_v4(x + (size_t)src * CDIM, g1, b1, As + r * AROW, lane);
        }
    } else {
        const bf16* Ap = (const bf16*)Ain;
        #pragma unroll
        for (int cid = t; cid < 1536; cid += 256) {
            int row = cid / 12, c = cid % 12;
            cp16(smem_u32(As + row * AROW + c * 8),
                 Ap + (size_t)(bm + row) * CDIM + c * 8);
        }
        cp_commit();
    }

    #pragma unroll
    for (int nc = 0; nc < NC; nc++) {
        if (nc + 1 < NC) { issueB(nc + 1, (nc + 1) & 1); cp_wait1(); }
        else             { cp_wait0(); }
        __syncthreads();
        const bf16* Bb = Bs + (nc & 1) * 96 * AROW;

        float acc[2][6][4];
        #pragma unroll
        for (int i = 0; i < 2; i++)
            #pragma unroll
            for (int j = 0; j < 6; j++)
                #pragma unroll
                for (int q = 0; q < 4; q++) acc[i][j][q] = 0.0f;

        #pragma unroll
        for (int ks = 0; ks < 96; ks += 16) {
            uint32_t af[2][4];
            #pragma unroll
            for (int mt = 0; mt < 2; mt++) {
                int row = wrow * 32 + mt * 16 + (lane & 15);
                int col = ks + ((lane >> 4) << 3);
                ldm_x4(af[mt][0], af[mt][1], af[mt][2], af[mt][3],
                       smem_u32(As + row * AROW + col));
            }
            uint32_t bfm[6][2];
            #pragma unroll
            for (int pr = 0; pr < 3; pr++) {
                int row = wcol * 48 + pr * 16 + (lane & 7) + ((lane >> 4) << 3);
                int col = ks + (((lane >> 3) & 1) << 3);
                uint32_t r0, r1, r2, r3;
                ldm_x4(r0, r1, r2, r3, smem_u32(Bb + row * AROW + col));
                bfm[pr*2  ][0] = r0; bfm[pr*2  ][1] = r1;
                bfm[pr*2+1][0] = r2; bfm[pr*2+1][1] = r3;
            }
            #pragma unroll
            for (int mt = 0; mt < 2; mt++)
                #pragma unroll
                for (int nt = 0; nt < 6; nt++)
                    mma_bf16(acc[mt][nt], af[mt], bfm[nt]);
        }

        #pragma unroll
        for (int mt = 0; mt < 2; mt++) {
            const int r0 = bm + wrow * 32 + mt * 16 + gid;
            const int r1 = r0 + 8;
            #pragma unroll
            for (int nt = 0; nt < 6; nt++) {
                const int col = nc * 96 + wcol * 48 + nt * 8 + tig * 2;
                const float b0 = bias[col], b1v = bias[col + 1];
                float v00 = acc[mt][nt][0] + b0;
                float v01 = acc[mt][nt][1] + b1v;
                float v10 = acc[mt][nt][2] + b0;
                float v11 = acc[mt][nt][3] + b1v;
                if (MODE == 2) {
                    v00 = 0.5f * v00 * (1.0f + erff(v00 * 0.70710678118654752f));
                    v01 = 0.5f * v01 * (1.0f + erff(v01 * 0.70710678118654752f));
                    v10 = 0.5f * v10 * (1.0f + erff(v10 * 0.70710678118654752f));
                    v11 = 0.5f * v11 * (1.0f + erff(v11 * 0.70710678118654752f));
                }
                *(__nv_bfloat162*)&Cout[(size_t)r0 * N + col] =
                    __nv_bfloat162(__float2bfloat16(v00), __float2bfloat16(v01));
                *(__nv_bfloat162*)&Cout[(size_t)r1 * N + col] =
                    __nv_bfloat162(__float2bfloat16(v10), __float2bfloat16(v11));
            }
        }
        __syncthreads();
    }
}

// ---------------- proj GEMM + window-reverse + residual + LN2 ---------------
#define SROW 40
__global__ void __launch_bounds__(256, 3)
proj_ln2(const bf16* __restrict__ A, const bf16* __restrict__ W,
         const float* __restrict__ bias, const float* __restrict__ xres,
         const float* __restrict__ g2, const float* __restrict__ b2,
         float* __restrict__ X1, bf16* __restrict__ H2)
{
    __shared__ bf16 As[2][128][SROW];
    __shared__ bf16 Bs[2][96][SROW];
    __shared__ float red_s[128][2];
    __shared__ float red_ss[128][2];

    const int t = threadIdx.x;
    const int bm = blockIdx.x * 128;
    const int warp = t >> 5, lane = t & 31;
    const int wrow = warp & 3, wcol = warp >> 2;
    const int gid = lane >> 2, tig = lane & 3;

    float acc[2][6][4];
    #pragma unroll
    for (int i = 0; i < 2; i++)
        #pragma unroll
        for (int j = 0; j < 6; j++)
            #pragma unroll
            for (int q = 0; q < 4; q++) acc[i][j][q] = 0.0f;

    auto issue = [&](int kt, int buf) {
        const int k0 = kt << 5;
        #pragma unroll
        for (int c = 0; c < 2; c++) {
            int cid = t + c * 256;
            int row = cid >> 2, cc = cid & 3;
            cp16(smem_u32(&As[buf][row][cc * 8]),
                 A + (size_t)(bm + row) * CDIM + k0 + cc * 8);
        }
        {
            int row = t >> 2, cc = t & 3;
            cp16(smem_u32(&Bs[buf][row][cc * 8]),
                 W + (size_t)row * CDIM + k0 + cc * 8);
        }
        if (t < 128) {
            int cid = 256 + t;
            int row = cid >> 2, cc = cid & 3;
            cp16(smem_u32(&Bs[buf][row][cc * 8]),
                 W + (size_t)row * CDIM + k0 + cc * 8);
        }
        cp_commit();
    };

    issue(0, 0);
    for (int kt = 0; kt < 3; kt++) {
        cp_wait0();
        __syncthreads();
        if (kt + 1 < 3) issue(kt + 1, (kt + 1) & 1);
        const int buf = kt & 1;
        #pragma unroll
        for (int ks = 0; ks < 32; ks += 16) {
            uint32_t af[2][4];
            #pragma unroll
            for (int mt = 0; mt < 2; mt++) {
                int row = wrow * 32 + mt * 16 + (lane & 15);
                int col = ks + ((lane >> 4) << 3);
                ldm_x4(af[mt][0], af[mt][1], af[mt][2], af[mt][3],
                       smem_u32(&As[buf][row][col]));
            }
            uint32_t bfm[6][2];
            #pragma unroll
            for (int pr = 0; pr < 3; pr++) {
                int row = wcol * 48 + pr * 16 + (lane & 7) + ((lane >> 4) << 3);
                int col = ks + (((lane >> 3) & 1) << 3);
                uint32_t r0, r1, r2, r3;
                ldm_x4(r0, r1, r2, r3, smem_u32(&Bs[buf][row][col]));
                bfm[pr*2  ][0] = r0; bfm[pr*2  ][1] = r1;
                bfm[pr*2+1][0] = r2; bfm[pr*2+1][1] = r3;
            }
            #pragma unroll
            for (int mt = 0; mt < 2; mt++)
                #pragma unroll
                for (int nt = 0; nt < 6; nt++)
                    mma_bf16(acc[mt][nt], af[mt], bfm[nt]);
        }
        __syncthreads();
    }

    #pragma unroll
    for (int mt = 0; mt < 2; mt++) {
        const int r0 = bm + wrow * 32 + mt * 16 + gid;
        const int r1 = r0 + 8;
        int w0 = (r0 >> 6) & 63, s0 = r0 & 63;
        int i0 = ((w0 >> 3) << 3) + (s0 >> 3), j0 = ((w0 & 7) << 3) + (s0 & 7);
        int d0 = (r0 & ~4095) | ((((i0 + SS) & 63) << 6) | ((j0 + SS) & 63));
        int w1 = (r1 >> 6) & 63, s1 = r1 & 63;
        int i1 = ((w1 >> 3) << 3) + (s1 >> 3), j1 = ((w1 & 7) << 3) + (s1 & 7);
        int d1 = (r1 & ~4095) | ((((i1 + SS) & 63) << 6) | ((j1 + SS) & 63));

        float sa = 0.f, ssa = 0.f, sb = 0.f, ssb = 0.f;
        #pragma unroll
        for (int nt = 0; nt < 6; nt++) {
            const int col = wcol * 48 + nt * 8 + tig * 2;
            const float b0 = bias[col], b1v = bias[col + 1];
            size_t o0 = (size_t)d0 * CDIM + col;
            size_t o1 = (size_t)d1 * CDIM + col;
            float2 x0 = *(const float2*)&xres[o0];
            float2 x1v = *(const float2*)&xres[o1];
            float v00 = acc[mt][nt][0] + b0 + x0.x;
            float v01 = acc[mt][nt][1] + b1v + x0.y;
            float v10 = acc[mt][nt][2] + b0 + x1v.x;
            float v11 = acc[mt][nt][3] + b1v + x1v.y;
            *(float2*)&X1[o0] = make_float2(v00, v01);
            *(float2*)&X1[o1] = make_float2(v10, v11);
            acc[mt][nt][0] = v00; acc[mt][nt][1] = v01;
            acc[mt][nt][2] = v10; acc[mt][nt][3] = v11;
            sa += v00 + v01;  ssa += v00*v00 + v01*v01;
            sb += v10 + v11;  ssb += v10*v10 + v11*v11;
        }
        #pragma unroll
        for (int o = 1; o <= 2; o <<= 1) {
            sa  += __shfl_xor_sync(0xffffffffu, sa,  o);
            ssa += __shfl_xor_sync(0xffffffffu, ssa, o);
            sb  += __shfl_xor_sync(0xffffffffu, sb,  o);
            ssb += __shfl_xor_sync(0xffffffffu, ssb, o);
        }
        if (tig == 0) {
            int lr = wrow * 32 + mt * 16 + gid;
            red_s [lr][wcol] = sa;  red_ss[lr][wcol] = ssa;
            red_s [lr + 8][wcol] = sb;  red_ss[lr + 8][wcol] = ssb;
        }
    }
    __syncthreads();

    #pragma unroll
    for (int mt = 0; mt < 2; mt++) {
        const int lr = wrow * 32 + mt * 16 + gid;
        const int r0 = bm + lr;
        const int r1 = r0 + 8;
        float mu0 = (red_s[lr][0] + red_s[lr][1]) * (1.0f/CDIM);
        float rs0 = rsqrtf((red_ss[lr][0] + red_ss[lr][1]) * (1.0f/CDIM)
                           - mu0*mu0 + 1e-5f);
        float mu1 = (red_s[lr+8][0] + red_s[lr+8][1]) * (1.0f/CDIM);
        float rs1 = rsqrtf((red_ss[lr+8][0] + red_ss[lr+8][1]) * (1.0f/CDIM)
                           - mu1*mu1 + 1e-5f);
        int w0 = (r0 >> 6) & 63, s0 = r0 & 63;
        int i0 = ((w0 >> 3) << 3) + (s0 >> 3), j0 = ((w0 & 7) << 3) + (s0 & 7);
        int d0 = (r0 & ~4095) | ((((i0 + SS) & 63) << 6) | ((j0 + SS) & 63));
        int w1 = (r1 >> 6) & 63, s1 = r1 & 63;
        int i1 = ((w1 >> 3) << 3) + (s1 >> 3), j1 = ((w1 & 7) << 3) + (s1 & 7);
        int d1 = (r1 & ~4095) | ((((i1 + SS) & 63) << 6) | ((j1 + SS) & 63));
        #pragma unroll
        for (int nt = 0; nt < 6; nt++) {
            const int col = wcol * 48 + nt * 8 + tig * 2;
            float gv0 = g2[col], gv1 = g2[col+1];
            float bv0 = b2[col], bv1 = b2[col+1];
            float h00 = (acc[mt][nt][0] - mu0) * rs0 * gv0 + bv0;
            float h01 = (acc[mt][nt][1] - mu0) * rs0 * gv1 + bv1;
            float h10 = (acc[mt][nt][2] - mu1) * rs1 * gv0 + bv0;
            float h11 = (acc[mt][nt][3] - mu1) * rs1 * gv1 + bv1;
            *(__nv_bfloat162*)&H2[(size_t)d0 * CDIM + col] =
                __nv_bfloat162(__float2bfloat16(h00), __float2bfloat16(h01));
            *(__nv_bfloat162*)&H2[(size_t)d1 * CDIM + col] =
                __nv_bfloat162(__float2bfloat16(h10), __float2bfloat16(h11));
        }
    }
}

// ---------------- FC2 GEMM (K=384, +x1 residual, f32 out) -------------------
__global__ void __launch_bounds__(256, 3)
fc2_gemm(const bf16* __restrict__ A, const bf16* __restrict__ W,
         const float* __restrict__ bias, const float* __restrict__ aux,
         float* __restrict__ Cout)
{
    __shared__ bf16 As[2][128][SROW];
    __shared__ bf16 Bs[2][96][SROW];

    const int t = threadIdx.x;
    const int bm = blockIdx.x * 128;
    const int warp = t >> 5, lane = t & 31;
    const int wrow = warp & 3, wcol = warp >> 2;
    const int gid = lane >> 2, tig = lane & 3;
    const int K = CH;

    float acc[2][6][4];
    #pragma unroll
    for (int i = 0; i < 2; i++)
        #pragma unroll
        for (int j = 0; j < 6; j++)
            #pragma unroll
            for (int q = 0; q < 4; q++) acc[i][j][q] = 0.0f;

    auto issue = [&](int kt, int buf) {
        const int k0 = kt << 5;
        #pragma unroll
        for (int c = 0; c < 2; c++) {
            int cid = t + c * 256;
            int row = cid >> 2, cc = cid & 3;
            cp16(smem_u32(&As[buf][row][cc * 8]),
                 A + (size_t)(bm + row) * K + k0 + cc * 8);
        }
        {
            int row = t >> 2, cc = t & 3;
            cp16(smem_u32(&Bs[buf][row][cc * 8]),
                 W + (size_t)row * K + k0 + cc * 8);
        }
        if (t < 128) {
            int cid = 256 + t;
            int row = cid >> 2, cc = cid & 3;
            cp16(smem_u32(&Bs[buf][row][cc * 8]),
                 W + (size_t)row * K + k0 + cc * 8);
        }
        cp_commit();
    };

    issue(0, 0);
    for (int kt = 0; kt < 12; kt++) {
        cp_wait0();
        __syncthreads();
        if (kt + 1 < 12) issue(kt + 1, (kt + 1) & 1);
        const int buf = kt & 1;
        #pragma unroll
        for (int ks = 0; ks < 32; ks += 16) {
            uint32_t af[2][4];
            #pragma unroll
            for (int mt = 0; mt < 2; mt++) {
                int row = wrow * 32 + mt * 16 + (lane & 15);
                int col = ks + ((lane >> 4) << 3);
                ldm_x4(af[mt][0], af[mt][1], af[mt][2], af[mt][3],
                       smem_u32(&As[buf][row][col]));
            }
            uint32_t bfm[6][2];
            #pragma unroll
            for (int pr = 0; pr < 3; pr++) {
                int row = wcol * 48 + pr * 16 + (lane & 7) + ((lane >> 4) << 3);
                int col = ks + (((lane >> 3) & 1) << 3);
                uint32_t r0, r1, r2, r3;
                ldm_x4(r0, r1, r2, r3, smem_u32(&Bs[buf][row][col]));
                bfm[pr*2  ][0] = r0; bfm[pr*2  ][1] = r1;
                bfm[pr*2+1][0] = r2; bfm[pr*2+1][1] = r3;
            }
            #pragma unroll
            for (int mt = 0; mt < 2; mt++)
                #pragma unroll
                for (int nt = 0; nt < 6; nt++)
                    mma_bf16(acc[mt][nt], af[mt], bfm[nt]);
        }
        __syncthreads();
    }

    #pragma unroll
    for (int mt = 0; mt < 2; mt++) {
        const int r0 = bm + wrow * 32 + mt * 16 + gid;
        const int r1 = r0 + 8;
        #pragma unroll
        for (int nt = 0; nt < 6; nt++) {
            const int col = wcol * 48 + nt * 8 + tig * 2;
            const float b0 = bias[col], b1v = bias[col + 1];
            float2 x0 = *(const float2*)&aux[(size_t)r0 * CDIM + col];
            float2 x1v = *(const float2*)&aux[(size_t)r1 * CDIM + col];
            *(float2*)&Cout[(size_t)r0 * CDIM + col] =
                make_float2(acc[mt][nt][0] + b0 + x0.x,
                            acc[mt][nt][1] + b1v + x0.y);
            *(float2*)&Cout[(size_t)r1 * CDIM + col] =
                make_float2(acc[mt][nt][2] + b0 + x1v.x,
                            acc[mt][nt][3] + b1v + x1v.y);
        }
    }
}

// ---------------- tensor-core windowed attention (reg-lean) -----------------
#define ATTN_SMEM (37888 + 18432)

__global__ void __launch_bounds__(256, 3)
attn_tc(const bf16* __restrict__ qkv, bf16* __restrict__ o)
{
    extern __shared__ __align__(16) char sm_[];
    bf16  (*S)[296]      = (bf16(*)[296])sm_;
    __half (*Vt)[32][72] = (__half(*)[32][72])(sm_ + 37888);

    const int win  = blockIdx.x;
    const int t    = threadIdx.x;
    const int warp = t >> 5, lane = t & 31;
    const int head = warp >> 1, mh = warp & 1;
    const int gid  = lane >> 2, tig = lane & 3;

    const bf16* wq = qkv + (size_t)win * 64 * C3;

    #pragma unroll
    for (int i = 0; i < 9; i++) {
        int cid = t + i * 256;
        int row = cid / 36, c = cid % 36;
        cp16(smem_u32(&S[row][c * 8]), wq + (size_t)row * C3 + c * 8);
    }
    cp_commit();
    cp_wait0();
    __syncthreads();

    {
        int tok = t & 63, h = t >> 6;
        const bf16* vsrc = &S[tok][192 + h * HD];
        #pragma unroll
        for (int d = 0; d < HD; d++)
            Vt[h][d][tok] = __float2half(__bfloat162float(vsrc[d]));
        Vt[h][24][tok] = __float2half(1.0f);
        #pragma unroll
        for (int d = 25; d < 32; d++)
            Vt[h][d][tok] = __float2half(0.0f);
    }

    const int qc = head * HD;
    const int kc = 96 + head * HD;

    // Q fragments via ldmatrix (persist: 16 regs)
    uint32_t aq[2][2][4];
    #pragma unroll
    for (int mt = 0; mt < 2; mt++) {
        #pragma unroll
        for (int kt = 0; kt < 2; kt++) {
            int row = mh * 32 + mt * 16 + (lane & 15);
            int col = qc + kt * 16 + ((lane >> 4) << 3);
            ldm_x4(aq[mt][kt][0], aq[mt][kt][1], aq[mt][kt][2], aq[mt][kt][3],
                   smem_u32(&S[row][col]));
        }
        aq[mt][1][2] = 0u; aq[mt][1][3] = 0u;   // dims 24..31 invalid
    }
    __syncthreads();   // Vt complete; S stays valid (disjoint regions)

    const int wimg = win & 63;
    const int cls = (((wimg >> 3) == 7) ? 2 : 0) | (((wimg & 7) == 7) ? 1 : 0);
    const float* bt = g_bias_exp + cls * 16384
                    + (((head * 2 + mh) * 2) * 8 * 32 + lane) * 4;

    const float K1 = 0.2944888985f;   // 24^-0.5 * log2(e)

    // ---- fused QK-mma + exp: per K-fragment pair, low register pressure ----
    uint32_t p01[2][8], p23[2][8];
    #pragma unroll
    for (int np = 0; np < 4; np++) {
        // K fragments for nt = 2np, 2np+1
        uint32_t k0r[4], k1a, k1c;
        {
            int row = np * 16 + (lane & 7) + ((lane >> 4) << 3);
            int col0 = kc + (((lane >> 3) & 1) << 3);
            ldm_x4(k0r[0], k0r[1], k0r[2], k0r[3], smem_u32(&S[row][col0]));
            uint32_t d1, d3;
            int col1 = kc + 16 + (((lane >> 3) & 1) << 3);
            ldm_x4(k1a, d1, k1c, d3, smem_u32(&S[row][col1]));
        }
        #pragma unroll
        for (int h2 = 0; h2 < 2; h2++) {
            const int nt = np * 2 + h2;
            uint32_t bk0[2] = { k0r[h2*2], k0r[h2*2+1] };
            uint32_t bk1[2] = { (h2 == 0) ? k1a : k1c, 0u };
            #pragma unroll
            for (int mt = 0; mt < 2; mt++) {
                float a4[4] = {0.f, 0.f, 0.f, 0.f};
                mma_bf16(a4, aq[mt][0], bk0);
                mma_bf16(a4, aq[mt][1], bk1);
                const float4 bb = *(const float4*)&bt[((mt * 8 + nt) * 32) << 2];
                float e00 = exp2_poly(a4[0] * K1 + bb.x);
                float e01 = exp2_poly(a4[1] * K1 + bb.y);
                float e10 = exp2_poly(a4[2] * K1 + bb.z);
                float e11 = exp2_poly(a4[3] * K1 + bb.w);
                __half2 h01 = __floats2half2_rn(e00, e01);
                __half2 h23 = __floats2half2_rn(e10, e11);
                p01[mt][nt] = *(uint32_t*)&h01;
                p23[mt][nt] = *(uint32_t*)&h23;
            }
        }
    }

    // ---- O = P @ V, V fragments loaded per k-tile (8 live regs) ----
    float ao[2][4][4];
    #pragma unroll
    for (int mt = 0; mt < 2; mt++)
        #pragma unroll
        for (int nv = 0; nv < 4; nv++)
            #pragma unroll
            for (int q = 0; q < 4; q++) ao[mt][nv][q] = 0.0f;

    #pragma unroll
    for (int kt = 0; kt < 4; kt++) {
        uint32_t bvk[4][2];
        #pragma unroll
        for (int np = 0; np < 2; np++) {
            int row = np * 16 + (lane & 7) + ((lane >> 4) << 3);
            int col = kt * 16 + (((lane >> 3) & 1) << 3);
            uint32_t r0, r1, r2, r3;
            ldm_x4(r0, r1, r2, r3, smem_u32(&Vt[head][row][col]));
            bvk[np*2  ][0] = r0; bvk[np*2  ][1] = r1;
            bvk[np*2+1][0] = r2; bvk[np*2+1][1] = r3;
        }
        #pragma unroll
        for (int mt = 0; mt < 2; mt++) {
            uint32_t ap[4] = { p01[mt][2*kt], p23[mt][2*kt],
                               p01[mt][2*kt+1], p23[mt][2*kt+1] };
            #pragma unroll
            for (int nv = 0; nv < 4; nv++)
                mma_f16(ao[mt][nv], ap, bvk[nv]);
        }
    }

    #pragma unroll
    for (int mt = 0; mt < 2; mt++) {
        float sum0 = __shfl_sync(0xffffffffu, ao[mt][3][0], lane & 28);
        float sum1 = __shfl_sync(0xffffffffu, ao[mt][3][2], lane & 28);
        float inv0 = __fdividef(1.0f, sum0);
        float inv1 = __fdividef(1.0f, sum1);
        int row0 = win * 64 + mh * 32 + mt * 16 + gid;
        #pragma unroll
        for (int nv = 0; nv < 3; nv++) {
            int col = head * HD + nv * 8 + tig * 2;
            *(__nv_bfloat162*)&o[(size_t)row0 * CDIM + col] =
                __nv_bfloat162(__float2bfloat16(ao[mt][nv][0] * inv0),
                               __float2bfloat16(ao[mt][nv][1] * inv0));
            *(__nv_bfloat162*)&o[(size_t)(row0 + 8) * CDIM + col] =
                __nv_bfloat162(__float2bfloat16(ao[mt][nv][2] * inv1),
                               __float2bfloat16(ao[mt][nv][3] * inv1));
        }
    }
}

// ---------------- launch ----------------------------------------------------
extern "C" void kernel_launch(void* const* d_in, const int* in_sizes, int n_in,
                              void* d_out, int out_size)
{
    const float* x       = (const float*)d_in[0];
    const float* norm1_g = (const float*)d_in[1];
    const float* norm1_b = (const float*)d_in[2];
    const float* qkv_w   = (const float*)d_in[3];
    const float* qkv_b   = (const float*)d_in[4];
    const float* rpb     = (const float*)d_in[5];
    const float* proj_w  = (const float*)d_in[6];
    const float* proj_b  = (const float*)d_in[7];
    const float* norm2_g = (const float*)d_in[8];
    const float* norm2_b = (const float*)d_in[9];
    const float* fc1_w   = (const float*)d_in[10];
    const float* fc1_b   = (const float*)d_in[11];
    const float* fc2_w   = (const float*)d_in[12];
    const float* fc2_b   = (const float*)d_in[13];
    float* out = (float*)d_out;

    bf16 *qkv_p, *o_p, *h2_p, *fc1_p;
    bf16 *wqkv_p, *wproj_p, *wfc1_p, *wfc2_p;
    float *x1_p;
    cudaGetSymbolAddress((void**)&qkv_p,  g_qkv);
    cudaGetSymbolAddress((void**)&o_p,    g_o);
    cudaGetSymbolAddress((void**)&x1_p,   g_x1);
    cudaGetSymbolAddress((void**)&h2_p,   g_h2);
    cudaGetSymbolAddress((void**)&fc1_p,  g_fc1);
    cudaGetSymbolAddress((void**)&wqkv_p, g_wqkv);
    cudaGetSymbolAddress((void**)&wproj_p,g_wproj);
    cudaGetSymbolAddress((void**)&wfc1_p, g_wfc1);
    cudaGetSymbolAddress((void**)&wfc2_p, g_wfc2);

    cudaFuncSetAttribute(attn_tc, cudaFuncAttributeMaxDynamicSharedMemorySize,
                         ATTN_SMEM);
    cudaFuncSetAttribute(gemm_nloop<0,3>,
                         cudaFuncAttributeMaxDynamicSharedMemorySize, NLOOP_SMEM);
    cudaFuncSetAttribute(gemm_nloop<2,4>,
                         cudaFuncAttributeMaxDynamicSharedMemorySize, NLOOP_SMEM);

    conv_weights<<<(CH*CDIM + 255)/256, 256>>>(qkv_w, proj_w, fc1_w, fc2_w);
    build_bias<<<256, 256>>>(rpb);

    // LN1 + shift/window + QKV (N-loop over 3 chunks of 96)
    gemm_nloop<0,3><<<TOKENS/128, 256, NLOOP_SMEM>>>(
        x, wqkv_p, qkv_b, norm1_g, norm1_b, qkv_p, C3);

    // windowed attention
    attn_tc<<<NWIN, 256, ATTN_SMEM>>>(qkv_p, o_p);

    // proj + window-reverse + residual + LN2 -> x1 (fp32), h2 (bf16)
    proj_ln2<<<TOKENS/128, 256>>>(o_p, wproj_p, proj_b, x,
                                  norm2_g, norm2_b, x1_p, h2_p);

    // FC1 + GELU (N-loop over 4 chunks of 96)
    gemm_nloop<2,4><<<TOKENS/128, 256, NLOOP_SMEM>>>(
        h2_p, wfc1_p, fc1_b, nullptr, nullptr, fc1_p, CH);

    // FC2 + residual -> out
    fc2_gemm<<<TOKENS/128, 256>>>(fc1_p, wfc2_p, fc2_b, x1_p, out);
}

// round 14
// speedup vs baseline: 1.0967x; 1.0967x over previous
#include <cuda_runtime.h>
#include <cuda_bf16.h>
#include <cuda_fp16.h>
#include <cstdint>
#include <cstddef>

// ---------------- static problem sizes -------------------------------------
#define SS      4
#define NH      4
#define CDIM    96
#define HD      24
#define NWIN    4096
#define TOKENS  262144
#define C3      288
#define CH      384

typedef __nv_bfloat16 bf16;

// ---------------- scratch ---------------------------------------------------
__device__ bf16  g_qkv[(size_t)TOKENS * C3];
__device__ bf16  g_o  [(size_t)TOKENS * CDIM];
__device__ float g_x1 [(size_t)TOKENS * CDIM];
__device__ bf16  g_h2 [(size_t)TOKENS * CDIM];
__device__ bf16  g_wqkv[C3 * CDIM];
__device__ bf16  g_wproj[CDIM * CDIM];
__device__ bf16  g_wfc1[CH * CDIM];
__device__ bf16  g_wfc2[CDIM * CH];
__device__ float g_bias_exp[4 * 16384];

// ---------------- asm helpers ----------------------------------------------
__device__ __forceinline__ uint32_t smem_u32(const void* p) {
    return (uint32_t)__cvta_generic_to_shared(p);
}
__device__ __forceinline__ void ldm_x4(uint32_t& r0, uint32_t& r1, uint32_t& r2,
                                       uint32_t& r3, uint32_t addr) {
    asm volatile("ldmatrix.sync.aligned.m8n8.x4.shared.b16 {%0,%1,%2,%3}, [%4];\n"
                 : "=r"(r0), "=r"(r1), "=r"(r2), "=r"(r3) : "r"(addr));
}
__device__ __forceinline__ void mma_bf16(float c[4], const uint32_t a[4],
                                         const uint32_t b[2]) {
    asm volatile(
        "mma.sync.aligned.m16n8k16.row.col.f32.bf16.bf16.f32 "
        "{%0,%1,%2,%3},{%4,%5,%6,%7},{%8,%9},{%0,%1,%2,%3};\n"
        : "+f"(c[0]), "+f"(c[1]), "+f"(c[2]), "+f"(c[3])
        : "r"(a[0]), "r"(a[1]), "r"(a[2]), "r"(a[3]), "r"(b[0]), "r"(b[1]));
}
__device__ __forceinline__ void mma_f16(float c[4], const uint32_t a[4],
                                        const uint32_t b[2]) {
    asm volatile(
        "mma.sync.aligned.m16n8k16.row.col.f32.f16.f16.f32 "
        "{%0,%1,%2,%3},{%4,%5,%6,%7},{%8,%9},{%0,%1,%2,%3};\n"
        : "+f"(c[0]), "+f"(c[1]), "+f"(c[2]), "+f"(c[3])
        : "r"(a[0]), "r"(a[1]), "r"(a[2]), "r"(a[3]), "r"(b[0]), "r"(b[1]));
}
__device__ __forceinline__ void cp16(uint32_t dst, const void* src) {
    asm volatile("cp.async.ca.shared.global [%0], [%1], 16;\n"
                 :: "r"(dst), "l"(src));
}
__device__ __forceinline__ void cp_commit() { asm volatile("cp.async.commit_group;\n"); }
__device__ __forceinline__ void cp_wait0() { asm volatile("cp.async.wait_group 0;\n"); }
__device__ __forceinline__ void cp_wait1() { asm volatile("cp.async.wait_group 1;\n"); }
template<int N>
__device__ __forceinline__ void cp_waitN() {
    asm volatile("cp.async.wait_group %0;\n" :: "n"(N));
}

__device__ __forceinline__ float exp2_poly(float z) {
    z = fmaxf(z, -100.0f);
    float t = z + 12582912.0f;
    int   n = __float_as_int(t) - 0x4B400000;
    float f = z - (t - 12582912.0f);
    float p = 0.009618129107f;
    p = p * f + 0.05550410866f;
    p = p * f + 0.2402265069f;
    p = p * f + 0.69314718056f;
    p = p * f + 1.0f;
    return p * __int_as_float((n + 127) << 23);
}
__device__ __forceinline__ float gelu_f(float v) {
    return 0.5f * v * (1.0f + erff(v * 0.70710678118654752f));
}

// ---------------- weight conversion -----------------------------------------
__global__ void conv_weights(const float* __restrict__ a, const float* __restrict__ b,
                             const float* __restrict__ c, const float* __restrict__ d)
{
    int i = blockIdx.x * 256 + threadIdx.x;
    if (i < C3 * CDIM)   g_wqkv[i]  = __float2bfloat16(a[i]);
    if (i < CDIM * CDIM) g_wproj[i] = __float2bfloat16(b[i]);
    if (i < CH * CDIM) { g_wfc1[i]  = __float2bfloat16(c[i]);
                         g_wfc2[i]  = __float2bfloat16(d[i]); }
}

// ---------------- bias+mask expansion (4 window classes) --------------------
__global__ void build_bias(const float* __restrict__ rpb)
{
    int idx = blockIdx.x * 256 + threadIdx.x;
    int cls = idx >> 14;
    int e   = idx & 16383;
    int q    = e & 3;
    int lane = (e >> 2) & 31;
    int nt   = (e >> 7) & 7;
    int mt   = (e >> 10) & 1;
    int mh   = (e >> 11) & 1;
    int head = (e >> 12) & 3;
    int gid = lane >> 2, tig = lane & 3;
    int n = mh*32 + mt*16 + gid + ((q >> 1) << 3);
    int m = nt*8 + tig*2 + (q & 1);
    int ni = n >> 3, nj = n & 7, mi = m >> 3, mj = m & 7;
    int ridx = (ni - mi + 7) * 15 + (nj - mj + 7);
    int wi7 = cls >> 1, wj7 = cls & 1;
    int rq = (wi7 ? ((ni < 4) ? 1 : 2) : 0) * 3 + (wj7 ? ((nj < 4) ? 1 : 2) : 0);
    int rk = (wi7 ? ((mi < 4) ? 1 : 2) : 0) * 3 + (wj7 ? ((mj < 4) ? 1 : 2) : 0);
    float mask = (rq != rk) ? -144.269504089f : 0.0f;
    g_bias_exp[idx] = rpb[ridx * NH + head] * 1.4426950408889634f + mask;
}

// ---------------- vectorized LN row helper ----------------------------------
__device__ __forceinline__ void ln_row_v4(const float* __restrict__ xr,
                                          const float* __restrict__ g,
                                          const float* __restrict__ b,
                                          bf16* __restrict__ orow, int lane)
{
    float4 v = make_float4(0.f, 0.f, 0.f, 0.f);
    if (lane < 24) v = *(const float4*)(xr + lane * 4);
    float s  = v.x + v.y + v.z + v.w;
    float ss = v.x*v.x + v.y*v.y + v.z*v.z + v.w*v.w;
    #pragma unroll
    for (int o = 16; o; o >>= 1) {
        s  += __shfl_xor_sync(0xffffffffu, s,  o);
        ss += __shfl_xor_sync(0xffffffffu, ss, o);
    }
    float mu = s * (1.0f/CDIM);
    float rs = rsqrtf(ss * (1.0f/CDIM) - mu*mu + 1e-5f);
    if (lane < 24) {
        float4 gv = *(const float4*)(g + lane * 4);
        float4 bv = *(const float4*)(b + lane * 4);
        __nv_bfloat162 lo((__nv_bfloat16)((v.x - mu) * rs * gv.x + bv.x),
                          (__nv_bfloat16)((v.y - mu) * rs * gv.y + bv.y));
        __nv_bfloat162 hi((__nv_bfloat16)((v.z - mu) * rs * gv.z + bv.z),
                          (__nv_bfloat16)((v.w - mu) * rs * gv.w + bv.w));
        uint2 pk;
        pk.x = *(uint32_t*)&lo;
        pk.y = *(uint32_t*)&hi;
        *(uint2*)(orow + lane * 4) = pk;
    }
}

// ---------------- QKV: LN1 + shift/window + N-loop GEMM (R12) ---------------
#define AROW 104
#define NLOOP_SMEM (128*AROW*2 + 2*96*AROW*2)

__global__ void __launch_bounds__(256, 3)
qkv_nloop(const float* __restrict__ x, const bf16* __restrict__ W,
          const float* __restrict__ bias,
          const float* __restrict__ g1, const float* __restrict__ b1,
          bf16* __restrict__ Cout)
{
    extern __shared__ __align__(16) char dyn[];
    bf16* As = (bf16*)dyn;
    bf16* Bs = (bf16*)(dyn + 128*AROW*2);

    const int t = threadIdx.x, warp = t >> 5, lane = t & 31;
    const int bm = blockIdx.x * 128;
    const int wrow = warp & 3, wcol = warp >> 2;
    const int gid = lane >> 2, tig = lane & 3;

    auto issueB = [&](int nc, int buf) {
        const bf16* Wb = W + (size_t)(nc * 96) * CDIM;
        bf16* Bd = Bs + buf * 96 * AROW;
        #pragma unroll
        for (int cid = t; cid < 1152; cid += 256) {
            int row = cid / 12, c = cid % 12;
            cp16(smem_u32(Bd + row * AROW + c * 8),
                 Wb + (size_t)row * CDIM + c * 8);
        }
        cp_commit();
    };

    issueB(0, 0);

    #pragma unroll
    for (int it = 0; it < 16; it++) {
        int r  = it * 8 + warp;
        int wr = bm + r;
        int w = (wr >> 6) & 63, s = wr & 63;
        int i0 = ((w >> 3) << 3) + (s >> 3), j0 = ((w & 7) << 3) + (s & 7);
        int src = (wr & ~4095) | ((((i0 + SS) & 63) << 6) | ((j0 + SS) & 63));
        ln_row_v4(x + (size_t)src * CDIM, g1, b1, As + r * AROW, lane);
    }

    #pragma unroll
    for (int nc = 0; nc < 3; nc++) {
        if (nc + 1 < 3) { issueB(nc + 1, (nc + 1) & 1); cp_wait1(); }
        else            { cp_wait0(); }
        __syncthreads();
        const bf16* Bb = Bs + (nc & 1) * 96 * AROW;

        float acc[2][6][4];
        #pragma unroll
        for (int i = 0; i < 2; i++)
            #pragma unroll
            for (int j = 0; j < 6; j++)
                #pragma unroll
                for (int q = 0; q < 4; q++) acc[i][j][q] = 0.0f;

        #pragma unroll
        for (int ks = 0; ks < 96; ks += 16) {
            uint32_t af[2][4];
            #pragma unroll
            for (int mt = 0; mt < 2; mt++) {
                int row = wrow * 32 + mt * 16 + (lane & 15);
                int col = ks + ((lane >> 4) << 3);
                ldm_x4(af[mt][0], af[mt][1], af[mt][2], af[mt][3],
                       smem_u32(As + row * AROW + col));
            }
            uint32_t bfm[6][2];
            #pragma unroll
            for (int pr = 0; pr < 3; pr++) {
                int row = wcol * 48 + pr * 16 + (lane & 7) + ((lane >> 4) << 3);
                int col = ks + (((lane >> 3) & 1) << 3);
                uint32_t r0, r1, r2, r3;
                ldm_x4(r0, r1, r2, r3, smem_u32(Bb + row * AROW + col));
                bfm[pr*2  ][0] = r0; bfm[pr*2  ][1] = r1;
                bfm[pr*2+1][0] = r2; bfm[pr*2+1][1] = r3;
            }
            #pragma unroll
            for (int mt = 0; mt < 2; mt++)
                #pragma unroll
                for (int nt = 0; nt < 6; nt++)
                    mma_bf16(acc[mt][nt], af[mt], bfm[nt]);
        }

        #pragma unroll
        for (int mt = 0; mt < 2; mt++) {
            const int r0 = bm + wrow * 32 + mt * 16 + gid;
            const int r1 = r0 + 8;
            #pragma unroll
            for (int nt = 0; nt < 6; nt++) {
                const int col = nc * 96 + wcol * 48 + nt * 8 + tig * 2;
                const float b0 = bias[col], b1v = bias[col + 1];
                *(__nv_bfloat162*)&Cout[(size_t)r0 * C3 + col] =
                    __nv_bfloat162(__float2bfloat16(acc[mt][nt][0] + b0),
                                   __float2bfloat16(acc[mt][nt][1] + b1v));
                *(__nv_bfloat162*)&Cout[(size_t)r1 * C3 + col] =
                    __nv_bfloat162(__float2bfloat16(acc[mt][nt][2] + b0),
                                   __float2bfloat16(acc[mt][nt][3] + b1v));
            }
        }
        __syncthreads();
    }
}

// ---------------- proj GEMM + window-reverse + residual + LN2 (R12) ---------
#define SROW 40
__global__ void __launch_bounds__(256, 3)
proj_ln2(const bf16* __restrict__ A, const bf16* __restrict__ W,
         const float* __restrict__ bias, const float* __restrict__ xres,
         const float* __restrict__ g2, const float* __restrict__ b2,
         float* __restrict__ X1, bf16* __restrict__ H2)
{
    __shared__ bf16 As[2][128][SROW];
    __shared__ bf16 Bs[2][96][SROW];
    __shared__ float red_s[128][2];
    __shared__ float red_ss[128][2];

    const int t = threadIdx.x;
    const int bm = blockIdx.x * 128;
    const int warp = t >> 5, lane = t & 31;
    const int wrow = warp & 3, wcol = warp >> 2;
    const int gid = lane >> 2, tig = lane & 3;

    float acc[2][6][4];
    #pragma unroll
    for (int i = 0; i < 2; i++)
        #pragma unroll
        for (int j = 0; j < 6; j++)
            #pragma unroll
            for (int q = 0; q < 4; q++) acc[i][j][q] = 0.0f;

    auto issue = [&](int kt, int buf) {
        const int k0 = kt << 5;
        #pragma unroll
        for (int c = 0; c < 2; c++) {
            int cid = t + c * 256;
            int row = cid >> 2, cc = cid & 3;
            cp16(smem_u32(&As[buf][row][cc * 8]),
                 A + (size_t)(bm + row) * CDIM + k0 + cc * 8);
        }
        {
            int row = t >> 2, cc = t & 3;
            cp16(smem_u32(&Bs[buf][row][cc * 8]),
                 W + (size_t)row * CDIM + k0 + cc * 8);
        }
        if (t < 128) {
            int cid = 256 + t;
            int row = cid >> 2, cc = cid & 3;
            cp16(smem_u32(&Bs[buf][row][cc * 8]),
                 W + (size_t)row * CDIM + k0 + cc * 8);
        }
        cp_commit();
    };

    issue(0, 0);
    for (int kt = 0; kt < 3; kt++) {
        cp_wait0();
        __syncthreads();
        if (kt + 1 < 3) issue(kt + 1, (kt + 1) & 1);
        const int buf = kt & 1;
        #pragma unroll
        for (int ks = 0; ks < 32; ks += 16) {
            uint32_t af[2][4];
            #pragma unroll
            for (int mt = 0; mt < 2; mt++) {
                int row = wrow * 32 + mt * 16 + (lane & 15);
                int col = ks + ((lane >> 4) << 3);
                ldm_x4(af[mt][0], af[mt][1], af[mt][2], af[mt][3],
                       smem_u32(&As[buf][row][col]));
            }
            uint32_t bfm[6][2];
            #pragma unroll
            for (int pr = 0; pr < 3; pr++) {
                int row = wcol * 48 + pr * 16 + (lane & 7) + ((lane >> 4) << 3);
                int col = ks + (((lane >> 3) & 1) << 3);
                uint32_t r0, r1, r2, r3;
                ldm_x4(r0, r1, r2, r3, smem_u32(&Bs[buf][row][col]));
                bfm[pr*2  ][0] = r0; bfm[pr*2  ][1] = r1;
                bfm[pr*2+1][0] = r2; bfm[pr*2+1][1] = r3;
            }
            #pragma unroll
            for (int mt = 0; mt < 2; mt++)
                #pragma unroll
                for (int nt = 0; nt < 6; nt++)
                    mma_bf16(acc[mt][nt], af[mt], bfm[nt]);
        }
        __syncthreads();
    }

    #pragma unroll
    for (int mt = 0; mt < 2; mt++) {
        const int r0 = bm + wrow * 32 + mt * 16 + gid;
        const int r1 = r0 + 8;
        int w0 = (r0 >> 6) & 63, s0 = r0 & 63;
        int i0 = ((w0 >> 3) << 3) + (s0 >> 3), j0 = ((w0 & 7) << 3) + (s0 & 7);
        int d0 = (r0 & ~4095) | ((((i0 + SS) & 63) << 6) | ((j0 + SS) & 63));
        int w1 = (r1 >> 6) & 63, s1 = r1 & 63;
        int i1 = ((w1 >> 3) << 3) + (s1 >> 3), j1 = ((w1 & 7) << 3) + (s1 & 7);
        int d1 = (r1 & ~4095) | ((((i1 + SS) & 63) << 6) | ((j1 + SS) & 63));

        float sa = 0.f, ssa = 0.f, sb = 0.f, ssb = 0.f;
        #pragma unroll
        for (int nt = 0; nt < 6; nt++) {
            const int col = wcol * 48 + nt * 8 + tig * 2;
            const float b0 = bias[col], b1v = bias[col + 1];
            size_t o0 = (size_t)d0 * CDIM + col;
            size_t o1 = (size_t)d1 * CDIM + col;
            float2 x0 = *(const float2*)&xres[o0];
            float2 x1v = *(const float2*)&xres[o1];
            float v00 = acc[mt][nt][0] + b0 + x0.x;
            float v01 = acc[mt][nt][1] + b1v + x0.y;
            float v10 = acc[mt][nt][2] + b0 + x1v.x;
            float v11 = acc[mt][nt][3] + b1v + x1v.y;
            *(float2*)&X1[o0] = make_float2(v00, v01);
            *(float2*)&X1[o1] = make_float2(v10, v11);
            acc[mt][nt][0] = v00; acc[mt][nt][1] = v01;
            acc[mt][nt][2] = v10; acc[mt][nt][3] = v11;
            sa += v00 + v01;  ssa += v00*v00 + v01*v01;
            sb += v10 + v11;  ssb += v10*v10 + v11*v11;
        }
        #pragma unroll
        for (int o = 1; o <= 2; o <<= 1) {
            sa  += __shfl_xor_sync(0xffffffffu, sa,  o);
            ssa += __shfl_xor_sync(0xffffffffu, ssa, o);
            sb  += __shfl_xor_sync(0xffffffffu, sb,  o);
            ssb += __shfl_xor_sync(0xffffffffu, ssb, o);
        }
        if (tig == 0) {
            int lr = wrow * 32 + mt * 16 + gid;
            red_s [lr][wcol] = sa;  red_ss[lr][wcol] = ssa;
            red_s [lr + 8][wcol] = sb;  red_ss[lr + 8][wcol] = ssb;
        }
    }
    __syncthreads();

    #pragma unroll
    for (int mt = 0; mt < 2; mt++) {
        const int lr = wrow * 32 + mt * 16 + gid;
        const int r0 = bm + lr;
        const int r1 = r0 + 8;
        float mu0 = (red_s[lr][0] + red_s[lr][1]) * (1.0f/CDIM);
        float rs0 = rsqrtf((red_ss[lr][0] + red_ss[lr][1]) * (1.0f/CDIM)
                           - mu0*mu0 + 1e-5f);
        float mu1 = (red_s[lr+8][0] + red_s[lr+8][1]) * (1.0f/CDIM);
        float rs1 = rsqrtf((red_ss[lr+8][0] + red_ss[lr+8][1]) * (1.0f/CDIM)
                           - mu1*mu1 + 1e-5f);
        int w0 = (r0 >> 6) & 63, s0 = r0 & 63;
        int i0 = ((w0 >> 3) << 3) + (s0 >> 3), j0 = ((w0 & 7) << 3) + (s0 & 7);
        int d0 = (r0 & ~4095) | ((((i0 + SS) & 63) << 6) | ((j0 + SS) & 63));
        int w1 = (r1 >> 6) & 63, s1 = r1 & 63;
        int i1 = ((w1 >> 3) << 3) + (s1 >> 3), j1 = ((w1 & 7) << 3) + (s1 & 7);
        int d1 = (r1 & ~4095) | ((((i1 + SS) & 63) << 6) | ((j1 + SS) & 63));
        #pragma unroll
        for (int nt = 0; nt < 6; nt++) {
            const int col = wcol * 48 + nt * 8 + tig * 2;
            float gv0 = g2[col], gv1 = g2[col+1];
            float bv0 = b2[col], bv1 = b2[col+1];
            float h00 = (acc[mt][nt][0] - mu0) * rs0 * gv0 + bv0;
            float h01 = (acc[mt][nt][1] - mu0) * rs0 * gv1 + bv1;
            float h10 = (acc[mt][nt][2] - mu1) * rs1 * gv0 + bv0;
            float h11 = (acc[mt][nt][3] - mu1) * rs1 * gv1 + bv1;
            *(__nv_bfloat162*)&H2[(size_t)d0 * CDIM + col] =
                __nv_bfloat162(__float2bfloat16(h00), __float2bfloat16(h01));
            *(__nv_bfloat162*)&H2[(size_t)d1 * CDIM + col] =
                __nv_bfloat162(__float2bfloat16(h10), __float2bfloat16(h11));
        }
    }
}

// ---------------- fused MLP: FC1+GELU (smem) -> FC2 + residual --------------
// BM=128, 4 N/K-chunks of 96. smem: As(h2) 26624 + Hs 26624 + 3 W bufs 59904.
// Weight ring: seq s: even=W1[s/2], odd=W2[s/2], buffer = s%3, prefetch depth 3.
#define MLP_SMEM (26624 + 26624 + 3*96*AROW*2)

__global__ void __launch_bounds__(256, 2)
mlp_fused(const bf16* __restrict__ h2, const float* __restrict__ fc1b,
          const float* __restrict__ fc2b, const float* __restrict__ x1,
          float* __restrict__ out)
{
    extern __shared__ __align__(16) char dyn[];
    bf16* As = (bf16*)dyn;                        // [128][104]
    bf16* Hs = (bf16*)(dyn + 26624);              // [128][104]
    bf16* Wb = (bf16*)(dyn + 53248);              // [3][96][104]

    const int t = threadIdx.x, warp = t >> 5, lane = t & 31;
    const int bm = blockIdx.x * 128;
    const int wrow = warp & 3, wcol = warp >> 2;
    const int gid = lane >> 2, tig = lane & 3;

    auto issueW1 = [&](int nc, int buf) {
        const bf16* src = g_wfc1 + (size_t)(nc * 96) * CDIM;
        bf16* Bd = Wb + buf * 96 * AROW;
        #pragma unroll
        for (int cid = t; cid < 1152; cid += 256) {
            int row = cid / 12, c = cid % 12;
            cp16(smem_u32(Bd + row * AROW + c * 8),
                 src + (size_t)row * CDIM + c * 8);
        }
        cp_commit();
    };
    auto issueW2 = [&](int nc, int buf) {
        const bf16* src = g_wfc2 + nc * 96;
        bf16* Bd = Wb + buf * 96 * AROW;
        #pragma unroll
        for (int cid = t; cid < 1152; cid += 256) {
            int row = cid / 12, c = cid % 12;
            cp16(smem_u32(Bd + row * AROW + c * 8),
                 src + (size_t)row * CH + c * 8);
        }
        cp_commit();
    };

    // G0: A tile (h2) + W1[0] -> b0
    {
        #pragma unroll
        for (int cid = t; cid < 1536; cid += 256) {
            int row = cid / 12, c = cid % 12;
            cp16(smem_u32(As + row * AROW + c * 8),
                 h2 + (size_t)(bm + row) * CDIM + c * 8);
        }
        const bf16* src = g_wfc1;
        #pragma unroll
        for (int cid = t; cid < 1152; cid += 256) {
            int row = cid / 12, c = cid % 12;
            cp16(smem_u32(Wb + row * AROW + c * 8),
                 src + (size_t)row * CDIM + c * 8);
        }
        cp_commit();
    }
    issueW2(0, 1);   // G1
    issueW1(1, 2);   // G2

    float oacc[2][6][4];
    #pragma unroll
    for (int i = 0; i < 2; i++)
        #pragma unroll
        for (int j = 0; j < 6; j++)
            #pragma unroll
            for (int q = 0; q < 4; q++) oacc[i][j][q] = 0.0f;

    #pragma unroll
    for (int nc = 0; nc < 4; nc++) {
        // ---- wait W1[nc] ----
        if (nc == 3) cp_waitN<1>(); else cp_waitN<2>();
        __syncthreads();
        const bf16* W1b = Wb + ((2 * nc) % 3) * 96 * AROW;

        // ---- FC1 chunk: facc = As @ W1[nc]^T ----
        float facc[2][6][4];
        #pragma unroll
        for (int i = 0; i < 2; i++)
            #pragma unroll
            for (int j = 0; j < 6; j++)
                #pragma unroll
                for (int q = 0; q < 4; q++) facc[i][j][q] = 0.0f;

        #pragma unroll
        for (int ks = 0; ks < 96; ks += 16) {
            uint32_t af[2][4];
            #pragma unroll
            for (int mt = 0; mt < 2; mt++) {
                int row = wrow * 32 + mt * 16 + (lane & 15);
                int col = ks + ((lane >> 4) << 3);
                ldm_x4(af[mt][0], af[mt][1], af[mt][2], af[mt][3],
                       smem_u32(As + row * AROW + col));
            }
            uint32_t bfm[6][2];
            #pragma unroll
            for (int pr = 0; pr < 3; pr++) {
                int row = wcol * 48 + pr * 16 + (lane & 7) + ((lane >> 4) << 3);
                int col = ks + (((lane >> 3) & 1) << 3);
                uint32_t r0, r1, r2, r3;
                ldm_x4(r0, r1, r2, r3, smem_u32(W1b + row * AROW + col));
                bfm[pr*2  ][0] = r0; bfm[pr*2  ][1] = r1;
                bfm[pr*2+1][0] = r2; bfm[pr*2+1][1] = r3;
            }
            #pragma unroll
            for (int mt = 0; mt < 2; mt++)
                #pragma unroll
                for (int nt = 0; nt < 6; nt++)
                    mma_bf16(facc[mt][nt], af[mt], bfm[nt]);
        }

        // ---- GELU -> Hs (local rows, cols 0..95) ----
        #pragma unroll
        for (int mt = 0; mt < 2; mt++) {
            const int lr = wrow * 32 + mt * 16 + gid;
            #pragma unroll
            for (int nt = 0; nt < 6; nt++) {
                const int col = wcol * 48 + nt * 8 + tig * 2;
                const float b0 = fc1b[nc * 96 + col], b1v = fc1b[nc * 96 + col + 1];
                float v00 = gelu_f(facc[mt][nt][0] + b0);
                float v01 = gelu_f(facc[mt][nt][1] + b1v);
                float v10 = gelu_f(facc[mt][nt][2] + b0);
                float v11 = gelu_f(facc[mt][nt][3] + b1v);
                *(__nv_bfloat162*)(Hs + lr * AROW + col) =
                    __nv_bfloat162(__float2bfloat16(v00), __float2bfloat16(v01));
                *(__nv_bfloat162*)(Hs + (lr + 8) * AROW + col) =
                    __nv_bfloat162(__float2bfloat16(v10), __float2bfloat16(v11));
            }
        }
        // ---- wait W2[nc] + make Hs visible ----
        if (nc == 3) cp_waitN<0>(); else cp_waitN<1>();
        __syncthreads();
        const bf16* W2b = Wb + ((2 * nc + 1) % 3) * 96 * AROW;

        // ---- FC2 chunk: oacc += Hs @ W2[nc]^T ----
        #pragma unroll
        for (int ks = 0; ks < 96; ks += 16) {
            uint32_t af[2][4];
            #pragma unroll
            for (int mt = 0; mt < 2; mt++) {
                int row = wrow * 32 + mt * 16 + (lane & 15);
                int col = ks + ((lane >> 4) << 3);
                ldm_x4(af[mt][0], af[mt][1], af[mt][2], af[mt][3],
                       smem_u32(Hs + row * AROW + col));
            }
            uint32_t bfm[6][2];
            #pragma unroll
            for (int pr = 0; pr < 3; pr++) {
                int row = wcol * 48 + pr * 16 + (lane & 7) + ((lane >> 4) << 3);
                int col = ks + (((lane >> 3) & 1) << 3);
                uint32_t r0, r1, r2, r3;
                ldm_x4(r0, r1, r2, r3, smem_u32(W2b + row * AROW + col));
                bfm[pr*2  ][0] = r0; bfm[pr*2  ][1] = r1;
                bfm[pr*2+1][0] = r2; bfm[pr*2+1][1] = r3;
            }
            #pragma unroll
            for (int mt = 0; mt < 2; mt++)
                #pragma unroll
                for (int nt = 0; nt < 6; nt++)
                    mma_bf16(oacc[mt][nt], af[mt], bfm[nt]);
        }
        __syncthreads();   // all reads of this nc's buffers done

        // ---- prefetch next ring entries ----
        if (nc == 0) { issueW2(1, 0); issueW1(2, 1); }
        else if (nc == 1) { issueW2(2, 2); issueW1(3, 0); }
        else if (nc == 2) { issueW2(3, 1); }
    }

    // ---- epilogue: bias + x1 residual -> out (fp32) ----
    #pragma unroll
    for (int mt = 0; mt < 2; mt++) {
        const int r0 = bm + wrow * 32 + mt * 16 + gid;
        const int r1 = r0 + 8;
        #pragma unroll
        for (int nt = 0; nt < 6; nt++) {
            const int col = wcol * 48 + nt * 8 + tig * 2;
            const float b0 = fc2b[col], b1v = fc2b[col + 1];
            float2 x0 = *(const float2*)&x1[(size_t)r0 * CDIM + col];
            float2 x1v = *(const float2*)&x1[(size_t)r1 * CDIM + col];
            *(float2*)&out[(size_t)r0 * CDIM + col] =
                make_float2(oacc[mt][nt][0] + b0 + x0.x,
                            oacc[mt][nt][1] + b1v + x0.y);
            *(float2*)&out[(size_t)r1 * CDIM + col] =
                make_float2(oacc[mt][nt][2] + b0 + x1v.x,
                            oacc[mt][nt][3] + b1v + x1v.y);
        }
    }
}

// ---------------- tensor-core windowed attention (R12 version) --------------
#define ATTN_SMEM (37888 + 18432)

__global__ void __launch_bounds__(256)
attn_tc(const bf16* __restrict__ qkv, bf16* __restrict__ o)
{
    extern __shared__ __align__(16) char sm_[];
    bf16  (*S)[296]      = (bf16(*)[296])sm_;
    __half (*Vt)[32][72] = (__half(*)[32][72])(sm_ + 37888);

    const int win  = blockIdx.x;
    const int t    = threadIdx.x;
    const int warp = t >> 5, lane = t & 31;
    const int head = warp >> 1, mh = warp & 1;
    const int gid  = lane >> 2, tig = lane & 3;

    const bf16* wq = qkv + (size_t)win * 64 * C3;

    #pragma unroll
    for (int i = 0; i < 9; i++) {
        int cid = t + i * 256;
        int row = cid / 36, c = cid % 36;
        cp16(smem_u32(&S[row][c * 8]), wq + (size_t)row * C3 + c * 8);
    }
    cp_commit();
    cp_wait0();
    __syncthreads();

    {
        int tok = t & 63, h = t >> 6;
        const bf16* vsrc = &S[tok][192 + h * HD];
        #pragma unroll
        for (int d = 0; d < HD; d++)
            Vt[h][d][tok] = __float2half(__bfloat162float(vsrc[d]));
        Vt[h][24][tok] = __float2half(1.0f);
        #pragma unroll
        for (int d = 25; d < 32; d++)
            Vt[h][d][tok] = __float2half(0.0f);
    }

    const int qc = head * HD;
    const int kc = 96 + head * HD;

    uint32_t aq[2][2][4];
    #pragma unroll
    for (int mt = 0; mt < 2; mt++) {
        #pragma unroll
        for (int kt = 0; kt < 2; kt++) {
            int row = mh * 32 + mt * 16 + (lane & 15);
            int col = qc + kt * 16 + ((lane >> 4) << 3);
            ldm_x4(aq[mt][kt][0], aq[mt][kt][1], aq[mt][kt][2], aq[mt][kt][3],
                   smem_u32(&S[row][col]));
        }
        aq[mt][1][2] = 0u; aq[mt][1][3] = 0u;
    }
    uint32_t bk[8][2][2];
    #pragma unroll
    for (int np = 0; np < 4; np++) {
        #pragma unroll
        for (int kt = 0; kt < 2; kt++) {
            int row = np * 16 + (lane & 7) + ((lane >> 4) << 3);
            int col = kc + kt * 16 + (((lane >> 3) & 1) << 3);
            uint32_t r0, r1, r2, r3;
            ldm_x4(r0, r1, r2, r3, smem_u32(&S[row][col]));
            bk[np*2  ][kt][0] = r0; bk[np*2  ][kt][1] = (kt == 0) ? r1 : 0u;
            bk[np*2+1][kt][0] = r2; bk[np*2+1][kt][1] = (kt == 0) ? r3 : 0u;
        }
    }
    __syncthreads();

    float acc[2][8][4];
    #pragma unroll
    for (int mt = 0; mt < 2; mt++)
        #pragma unroll
        for (int nt = 0; nt < 8; nt++)
            #pragma unroll
            for (int q = 0; q < 4; q++) acc[mt][nt][q] = 0.0f;

    #pragma unroll
    for (int mt = 0; mt < 2; mt++)
        #pragma unroll
        for (int nt = 0; nt < 8; nt++)
            #pragma unroll
            for (int kt = 0; kt < 2; kt++)
                mma_bf16(acc[mt][nt], aq[mt][kt], bk[nt][kt]);

    const int wimg = win & 63;
    const int cls = (((wimg >> 3) == 7) ? 2 : 0) | (((wimg & 7) == 7) ? 1 : 0);
    const float* bt = g_bias_exp + cls * 16384;

    const float K1 = 0.2944888985f;

    uint32_t p01[2][8], p23[2][8];
    #pragma unroll
    for (int mt = 0; mt < 2; mt++) {
        #pragma unroll
        for (int nt = 0; nt < 8; nt++) {
            const float4 bb = *(const float4*)&bt[
                (((((head * 2 + mh) * 2 + mt) * 8 + nt) * 32 + lane) << 2)];
            float e00 = exp2_poly(acc[mt][nt][0] * K1 + bb.x);
            float e01 = exp2_poly(acc[mt][nt][1] * K1 + bb.y);
            float e10 = exp2_poly(acc[mt][nt][2] * K1 + bb.z);
            float e11 = exp2_poly(acc[mt][nt][3] * K1 + bb.w);
            __half2 h01 = __floats2half2_rn(e00, e01);
            __half2 h23 = __floats2half2_rn(e10, e11);
            p01[mt][nt] = *(uint32_t*)&h01;
            p23[mt][nt] = *(uint32_t*)&h23;
        }
    }

    uint32_t bv[4][4][2];
    #pragma unroll
    for (int np = 0; np < 2; np++) {
        #pragma unroll
        for (int kt = 0; kt < 4; kt++) {
            int row = np * 16 + (lane & 7) + ((lane >> 4) << 3);
            int col = kt * 16 + (((lane >> 3) & 1) << 3);
            uint32_t r0, r1, r2, r3;
            ldm_x4(r0, r1, r2, r3, smem_u32(&Vt[head][row][col]));
            bv[np*2  ][kt][0] = r0; bv[np*2  ][kt][1] = r1;
            bv[np*2+1][kt][0] = r2; bv[np*2+1][kt][1] = r3;
        }
    }

    float ao[2][4][4];
    #pragma unroll
    for (int mt = 0; mt < 2; mt++)
        #pragma unroll
        for (int nv = 0; nv < 4; nv++)
            #pragma unroll
            for (int q = 0; q < 4; q++) ao[mt][nv][q] = 0.0f;

    #pragma unroll
    for (int mt = 0; mt < 2; mt++) {
        #pragma unroll
        for (int kt = 0; kt < 4; kt++) {
            uint32_t ap[4] = { p01[mt][2*kt], p23[mt][2*kt],
                               p01[mt][2*kt+1], p23[mt][2*kt+1] };
            #pragma unroll
            for (int nv = 0; nv < 4; nv++)
                mma_f16(ao[mt][nv], ap, bv[nv][kt]);
        }
    }

    #pragma unroll
    for (int mt = 0; mt < 2; mt++) {
        float sum0 = __shfl_sync(0xffffffffu, ao[mt][3][0], lane & 28);
        float sum1 = __shfl_sync(0xffffffffu, ao[mt][3][2], lane & 28);
        float inv0 = __fdividef(1.0f, sum0);
        float inv1 = __fdividef(1.0f, sum1);
        int row0 = win * 64 + mh * 32 + mt * 16 + gid;
        #pragma unroll
        for (int nv = 0; nv < 3; nv++) {
            int col = head * HD + nv * 8 + tig * 2;
            *(__nv_bfloat162*)&o[(size_t)row0 * CDIM + col] =
                __nv_bfloat162(__float2bfloat16(ao[mt][nv][0] * inv0),
                               __float2bfloat16(ao[mt][nv][1] * inv0));
            *(__nv_bfloat162*)&o[(size_t)(row0 + 8) * CDIM + col] =
                __nv_bfloat162(__float2bfloat16(ao[mt][nv][2] * inv1),
                               __float2bfloat16(ao[mt][nv][3] * inv1));
        }
    }
}

// ---------------- launch ----------------------------------------------------
extern "C" void kernel_launch(void* const* d_in, const int* in_sizes, int n_in,
                              void* d_out, int out_size)
{
    const float* x       = (const float*)d_in[0];
    const float* norm1_g = (const float*)d_in[1];
    const float* norm1_b = (const float*)d_in[2];
    const float* qkv_w   = (const float*)d_in[3];
    const float* qkv_b   = (const float*)d_in[4];
    const float* rpb     = (const float*)d_in[5];
    const float* proj_w  = (const float*)d_in[6];
    const float* proj_b  = (const float*)d_in[7];
    const float* norm2_g = (const float*)d_in[8];
    const float* norm2_b = (const float*)d_in[9];
    const float* fc1_w   = (const float*)d_in[10];
    const float* fc1_b   = (const float*)d_in[11];
    const float* fc2_w   = (const float*)d_in[12];
    const float* fc2_b   = (const float*)d_in[13];
    float* out = (float*)d_out;

    bf16 *qkv_p, *o_p, *h2_p;
    bf16 *wqkv_p, *wproj_p;
    float *x1_p;
    cudaGetSymbolAddress((void**)&qkv_p,  g_qkv);
    cudaGetSymbolAddress((void**)&o_p,    g_o);
    cudaGetSymbolAddress((void**)&x1_p,   g_x1);
    cudaGetSymbolAddress((void**)&h2_p,   g_h2);
    cudaGetSymbolAddress((void**)&wqkv_p, g_wqkv);
    cudaGetSymbolAddress((void**)&wproj_p,g_wproj);

    cudaFuncSetAttribute(attn_tc, cudaFuncAttributeMaxDynamicSharedMemorySize,
                         ATTN_SMEM);
    cudaFuncSetAttribute(qkv_nloop,
                         cudaFuncAttributeMaxDynamicSharedMemorySize, NLOOP_SMEM);
    cudaFuncSetAttribute(mlp_fused,
                         cudaFuncAttributeMaxDynamicSharedMemorySize, MLP_SMEM);

    conv_weights<<<(CH*CDIM + 255)/256, 256>>>(qkv_w, proj_w, fc1_w, fc2_w);
    build_bias<<<256, 256>>>(rpb);

    // LN1 + shift/window + QKV
    qkv_nloop<<<TOKENS/128, 256, NLOOP_SMEM>>>(
        x, wqkv_p, qkv_b, norm1_g, norm1_b, qkv_p);

    // windowed attention
    attn_tc<<<NWIN, 256, ATTN_SMEM>>>(qkv_p, o_p);

    // proj + window-reverse + residual + LN2 -> x1 (fp32), h2 (bf16)
    proj_ln2<<<TOKENS/128, 256>>>(o_p, wproj_p, proj_b, x,
                                  norm2_g, norm2_b, x1_p, h2_p);

    // fused FC1 + GELU + FC2 + residual -> out
    mlp_fused<<<TOKENS/128, 256, MLP_SMEM>>>(h2_p, fc1_b, fc2_b, x1_p, out);
}

// round 15
// speedup vs baseline: 1.0986x; 1.0017x over previous
#include <cuda_runtime.h>
#include <cuda_bf16.h>
#include <cuda_fp16.h>
#include <cstdint>
#include <cstddef>

// ---------------- static problem sizes -------------------------------------
#define SS      4
#define NH      4
#define CDIM    96
#define HD      24
#define NWIN    4096
#define TOKENS  262144
#define C3      288
#define CH      384

typedef __nv_bfloat16 bf16;

// ---------------- scratch ---------------------------------------------------
__device__ bf16  g_qkv[(size_t)TOKENS * C3];
__device__ bf16  g_o  [(size_t)TOKENS * CDIM];
__device__ float g_x1 [(size_t)TOKENS * CDIM];
__device__ bf16  g_h2 [(size_t)TOKENS * CDIM];
__device__ bf16  g_wqkv[C3 * CDIM];
__device__ bf16  g_wproj[CDIM * CDIM];
__device__ bf16  g_wfc1[CH * CDIM];
__device__ bf16  g_wfc2[CDIM * CH];
__device__ float g_bias_exp[4 * 16384];

// ---------------- asm helpers ----------------------------------------------
__device__ __forceinline__ uint32_t smem_u32(const void* p) {
    return (uint32_t)__cvta_generic_to_shared(p);
}
__device__ __forceinline__ void ldm_x4(uint32_t& r0, uint32_t& r1, uint32_t& r2,
                                       uint32_t& r3, uint32_t addr) {
    asm volatile("ldmatrix.sync.aligned.m8n8.x4.shared.b16 {%0,%1,%2,%3}, [%4];\n"
                 : "=r"(r0), "=r"(r1), "=r"(r2), "=r"(r3) : "r"(addr));
}
__device__ __forceinline__ void ldm_x4_t(uint32_t& r0, uint32_t& r1, uint32_t& r2,
                                         uint32_t& r3, uint32_t addr) {
    asm volatile("ldmatrix.sync.aligned.m8n8.x4.trans.shared.b16 {%0,%1,%2,%3}, [%4];\n"
                 : "=r"(r0), "=r"(r1), "=r"(r2), "=r"(r3) : "r"(addr));
}
__device__ __forceinline__ void mma_bf16(float c[4], const uint32_t a[4],
                                         const uint32_t b[2]) {
    asm volatile(
        "mma.sync.aligned.m16n8k16.row.col.f32.bf16.bf16.f32 "
        "{%0,%1,%2,%3},{%4,%5,%6,%7},{%8,%9},{%0,%1,%2,%3};\n"
        : "+f"(c[0]), "+f"(c[1]), "+f"(c[2]), "+f"(c[3])
        : "r"(a[0]), "r"(a[1]), "r"(a[2]), "r"(a[3]), "r"(b[0]), "r"(b[1]));
}
__device__ __forceinline__ void cp16(uint32_t dst, const void* src) {
    asm volatile("cp.async.ca.shared.global [%0], [%1], 16;\n"
                 :: "r"(dst), "l"(src));
}
__device__ __forceinline__ void cp_commit() { asm volatile("cp.async.commit_group;\n"); }
__device__ __forceinline__ void cp_wait0() { asm volatile("cp.async.wait_group 0;\n"); }
__device__ __forceinline__ void cp_wait1() { asm volatile("cp.async.wait_group 1;\n"); }
template<int N>
__device__ __forceinline__ void cp_waitN() {
    asm volatile("cp.async.wait_group %0;\n" :: "n"(N));
}

__device__ __forceinline__ float exp2_poly(float z) {
    z = fmaxf(z, -100.0f);
    float t = z + 12582912.0f;
    int   n = __float_as_int(t) - 0x4B400000;
    float f = z - (t - 12582912.0f);
    float p = 0.009618129107f;
    p = p * f + 0.05550410866f;
    p = p * f + 0.2402265069f;
    p = p * f + 0.69314718056f;
    p = p * f + 1.0f;
    return p * __int_as_float((n + 127) << 23);
}
__device__ __forceinline__ float gelu_f(float v) {
    return 0.5f * v * (1.0f + erff(v * 0.70710678118654752f));
}

// ---------------- weight conversion -----------------------------------------
__global__ void conv_weights(const float* __restrict__ a, const float* __restrict__ b,
                             const float* __restrict__ c, const float* __restrict__ d)
{
    int i = blockIdx.x * 256 + threadIdx.x;
    if (i < C3 * CDIM)   g_wqkv[i]  = __float2bfloat16(a[i]);
    if (i < CDIM * CDIM) g_wproj[i] = __float2bfloat16(b[i]);
    if (i < CH * CDIM) { g_wfc1[i]  = __float2bfloat16(c[i]);
                         g_wfc2[i]  = __float2bfloat16(d[i]); }
}

// ---------------- bias+mask expansion (4 window classes) --------------------
__global__ void build_bias(const float* __restrict__ rpb)
{
    int idx = blockIdx.x * 256 + threadIdx.x;
    int cls = idx >> 14;
    int e   = idx & 16383;
    int q    = e & 3;
    int lane = (e >> 2) & 31;
    int nt   = (e >> 7) & 7;
    int mt   = (e >> 10) & 1;
    int mh   = (e >> 11) & 1;
    int head = (e >> 12) & 3;
    int gid = lane >> 2, tig = lane & 3;
    int n = mh*32 + mt*16 + gid + ((q >> 1) << 3);
    int m = nt*8 + tig*2 + (q & 1);
    int ni = n >> 3, nj = n & 7, mi = m >> 3, mj = m & 7;
    int ridx = (ni - mi + 7) * 15 + (nj - mj + 7);
    int wi7 = cls >> 1, wj7 = cls & 1;
    int rq = (wi7 ? ((ni < 4) ? 1 : 2) : 0) * 3 + (wj7 ? ((nj < 4) ? 1 : 2) : 0);
    int rk = (wi7 ? ((mi < 4) ? 1 : 2) : 0) * 3 + (wj7 ? ((mj < 4) ? 1 : 2) : 0);
    float mask = (rq != rk) ? -144.269504089f : 0.0f;
    g_bias_exp[idx] = rpb[ridx * NH + head] * 1.4426950408889634f + mask;
}

// ---------------- vectorized LN row helper ----------------------------------
__device__ __forceinline__ void ln_row_v4(const float* __restrict__ xr,
                                          const float* __restrict__ g,
                                          const float* __restrict__ b,
                                          bf16* __restrict__ orow, int lane)
{
    float4 v = make_float4(0.f, 0.f, 0.f, 0.f);
    if (lane < 24) v = *(const float4*)(xr + lane * 4);
    float s  = v.x + v.y + v.z + v.w;
    float ss = v.x*v.x + v.y*v.y + v.z*v.z + v.w*v.w;
    #pragma unroll
    for (int o = 16; o; o >>= 1) {
        s  += __shfl_xor_sync(0xffffffffu, s,  o);
        ss += __shfl_xor_sync(0xffffffffu, ss, o);
    }
    float mu = s * (1.0f/CDIM);
    float rs = rsqrtf(ss * (1.0f/CDIM) - mu*mu + 1e-5f);
    if (lane < 24) {
        float4 gv = *(const float4*)(g + lane * 4);
        float4 bv = *(const float4*)(b + lane * 4);
        __nv_bfloat162 lo((__nv_bfloat16)((v.x - mu) * rs * gv.x + bv.x),
                          (__nv_bfloat16)((v.y - mu) * rs * gv.y + bv.y));
        __nv_bfloat162 hi((__nv_bfloat16)((v.z - mu) * rs * gv.z + bv.z),
                          (__nv_bfloat16)((v.w - mu) * rs * gv.w + bv.w));
        uint2 pk;
        pk.x = *(uint32_t*)&lo;
        pk.y = *(uint32_t*)&hi;
        *(uint2*)(orow + lane * 4) = pk;
    }
}

// ---------------- QKV: LN1 + shift/window + N-loop GEMM ---------------------
#define AROW 104
#define NLOOP_SMEM (128*AROW*2 + 2*96*AROW*2)

__global__ void __launch_bounds__(256, 3)
qkv_nloop(const float* __restrict__ x, const bf16* __restrict__ W,
          const float* __restrict__ bias,
          const float* __restrict__ g1, const float* __restrict__ b1,
          bf16* __restrict__ Cout)
{
    extern __shared__ __align__(16) char dyn[];
    bf16* As = (bf16*)dyn;
    bf16* Bs = (bf16*)(dyn + 128*AROW*2);

    const int t = threadIdx.x, warp = t >> 5, lane = t & 31;
    const int bm = blockIdx.x * 128;
    const int wrow = warp & 3, wcol = warp >> 2;
    const int gid = lane >> 2, tig = lane & 3;

    auto issueB = [&](int nc, int buf) {
        const bf16* Wb = W + (size_t)(nc * 96) * CDIM;
        bf16* Bd = Bs + buf * 96 * AROW;
        #pragma unroll
        for (int cid = t; cid < 1152; cid += 256) {
            int row = cid / 12, c = cid % 12;
            cp16(smem_u32(Bd + row * AROW + c * 8),
                 Wb + (size_t)row * CDIM + c * 8);
        }
        cp_commit();
    };

    issueB(0, 0);

    #pragma unroll
    for (int it = 0; it < 16; it++) {
        int r  = it * 8 + warp;
        int wr = bm + r;
        int w = (wr >> 6) & 63, s = wr & 63;
        int i0 = ((w >> 3) << 3) + (s >> 3), j0 = ((w & 7) << 3) + (s & 7);
        int src = (wr & ~4095) | ((((i0 + SS) & 63) << 6) | ((j0 + SS) & 63));
        ln_row_v4(x + (size_t)src * CDIM, g1, b1, As + r * AROW, lane);
    }

    #pragma unroll
    for (int nc = 0; nc < 3; nc++) {
        if (nc + 1 < 3) { issueB(nc + 1, (nc + 1) & 1); cp_wait1(); }
        else            { cp_wait0(); }
        __syncthreads();
        const bf16* Bb = Bs + (nc & 1) * 96 * AROW;

        float acc[2][6][4];
        #pragma unroll
        for (int i = 0; i < 2; i++)
            #pragma unroll
            for (int j = 0; j < 6; j++)
                #pragma unroll
                for (int q = 0; q < 4; q++) acc[i][j][q] = 0.0f;

        #pragma unroll
        for (int ks = 0; ks < 96; ks += 16) {
            uint32_t af[2][4];
            #pragma unroll
            for (int mt = 0; mt < 2; mt++) {
                int row = wrow * 32 + mt * 16 + (lane & 15);
                int col = ks + ((lane >> 4) << 3);
                ldm_x4(af[mt][0], af[mt][1], af[mt][2], af[mt][3],
                       smem_u32(As + row * AROW + col));
            }
            uint32_t bfm[6][2];
            #pragma unroll
            for (int pr = 0; pr < 3; pr++) {
                int row = wcol * 48 + pr * 16 + (lane & 7) + ((lane >> 4) << 3);
                int col = ks + (((lane >> 3) & 1) << 3);
                uint32_t r0, r1, r2, r3;
                ldm_x4(r0, r1, r2, r3, smem_u32(Bb + row * AROW + col));
                bfm[pr*2  ][0] = r0; bfm[pr*2  ][1] = r1;
                bfm[pr*2+1][0] = r2; bfm[pr*2+1][1] = r3;
            }
            #pragma unroll
            for (int mt = 0; mt < 2; mt++)
                #pragma unroll
                for (int nt = 0; nt < 6; nt++)
                    mma_bf16(acc[mt][nt], af[mt], bfm[nt]);
        }

        #pragma unroll
        for (int mt = 0; mt < 2; mt++) {
            const int r0 = bm + wrow * 32 + mt * 16 + gid;
            const int r1 = r0 + 8;
            #pragma unroll
            for (int nt = 0; nt < 6; nt++) {
                const int col = nc * 96 + wcol * 48 + nt * 8 + tig * 2;
                const float b0 = bias[col], b1v = bias[col + 1];
                *(__nv_bfloat162*)&Cout[(size_t)r0 * C3 + col] =
                    __nv_bfloat162(__float2bfloat16(acc[mt][nt][0] + b0),
                                   __float2bfloat16(acc[mt][nt][1] + b1v));
                *(__nv_bfloat162*)&Cout[(size_t)r1 * C3 + col] =
                    __nv_bfloat162(__float2bfloat16(acc[mt][nt][2] + b0),
                                   __float2bfloat16(acc[mt][nt][3] + b1v));
            }
        }
        __syncthreads();
    }
}

// ---------------- proj GEMM + window-reverse + residual + LN2 ---------------
#define SROW 40
__global__ void __launch_bounds__(256, 3)
proj_ln2(const bf16* __restrict__ A, const bf16* __restrict__ W,
         const float* __restrict__ bias, const float* __restrict__ xres,
         const float* __restrict__ g2, const float* __restrict__ b2,
         float* __restrict__ X1, bf16* __restrict__ H2)
{
    __shared__ bf16 As[2][128][SROW];
    __shared__ bf16 Bs[2][96][SROW];
    __shared__ float red_s[128][2];
    __shared__ float red_ss[128][2];

    const int t = threadIdx.x;
    const int bm = blockIdx.x * 128;
    const int warp = t >> 5, lane = t & 31;
    const int wrow = warp & 3, wcol = warp >> 2;
    const int gid = lane >> 2, tig = lane & 3;

    float acc[2][6][4];
    #pragma unroll
    for (int i = 0; i < 2; i++)
        #pragma unroll
        for (int j = 0; j < 6; j++)
            #pragma unroll
            for (int q = 0; q < 4; q++) acc[i][j][q] = 0.0f;

    auto issue = [&](int kt, int buf) {
        const int k0 = kt << 5;
        #pragma unroll
        for (int c = 0; c < 2; c++) {
            int cid = t + c * 256;
            int row = cid >> 2, cc = cid & 3;
            cp16(smem_u32(&As[buf][row][cc * 8]),
                 A + (size_t)(bm + row) * CDIM + k0 + cc * 8);
        }
        {
            int row = t >> 2, cc = t & 3;
            cp16(smem_u32(&Bs[buf][row][cc * 8]),
                 W + (size_t)row * CDIM + k0 + cc * 8);
        }
        if (t < 128) {
            int cid = 256 + t;
            int row = cid >> 2, cc = cid & 3;
            cp16(smem_u32(&Bs[buf][row][cc * 8]),
                 W + (size_t)row * CDIM + k0 + cc * 8);
        }
        cp_commit();
    };

    issue(0, 0);
    for (int kt = 0; kt < 3; kt++) {
        cp_wait0();
        __syncthreads();
        if (kt + 1 < 3) issue(kt + 1, (kt + 1) & 1);
        const int buf = kt & 1;
        #pragma unroll
        for (int ks = 0; ks < 32; ks += 16) {
            uint32_t af[2][4];
            #pragma unroll
            for (int mt = 0; mt < 2; mt++) {
                int row = wrow * 32 + mt * 16 + (lane & 15);
                int col = ks + ((lane >> 4) << 3);
                ldm_x4(af[mt][0], af[mt][1], af[mt][2], af[mt][3],
                       smem_u32(&As[buf][row][col]));
            }
            uint32_t bfm[6][2];
            #pragma unroll
            for (int pr = 0; pr < 3; pr++) {
                int row = wcol * 48 + pr * 16 + (lane & 7) + ((lane >> 4) << 3);
                int col = ks + (((lane >> 3) & 1) << 3);
                uint32_t r0, r1, r2, r3;
                ldm_x4(r0, r1, r2, r3, smem_u32(&Bs[buf][row][col]));
                bfm[pr*2  ][0] = r0; bfm[pr*2  ][1] = r1;
                bfm[pr*2+1][0] = r2; bfm[pr*2+1][1] = r3;
            }
            #pragma unroll
            for (int mt = 0; mt < 2; mt++)
                #pragma unroll
                for (int nt = 0; nt < 6; nt++)
                    mma_bf16(acc[mt][nt], af[mt], bfm[nt]);
        }
        __syncthreads();
    }

    #pragma unroll
    for (int mt = 0; mt < 2; mt++) {
        const int r0 = bm + wrow * 32 + mt * 16 + gid;
        const int r1 = r0 + 8;
        int w0 = (r0 >> 6) & 63, s0 = r0 & 63;
        int i0 = ((w0 >> 3) << 3) + (s0 >> 3), j0 = ((w0 & 7) << 3) + (s0 & 7);
        int d0 = (r0 & ~4095) | ((((i0 + SS) & 63) << 6) | ((j0 + SS) & 63));
        int w1 = (r1 >> 6) & 63, s1 = r1 & 63;
        int i1 = ((w1 >> 3) << 3) + (s1 >> 3), j1 = ((w1 & 7) << 3) + (s1 & 7);
        int d1 = (r1 & ~4095) | ((((i1 + SS) & 63) << 6) | ((j1 + SS) & 63));

        float sa = 0.f, ssa = 0.f, sb = 0.f, ssb = 0.f;
        #pragma unroll
        for (int nt = 0; nt < 6; nt++) {
            const int col = wcol * 48 + nt * 8 + tig * 2;
            const float b0 = bias[col], b1v = bias[col + 1];
            size_t o0 = (size_t)d0 * CDIM + col;
            size_t o1 = (size_t)d1 * CDIM + col;
            float2 x0 = *(const float2*)&xres[o0];
            float2 x1v = *(const float2*)&xres[o1];
            float v00 = acc[mt][nt][0] + b0 + x0.x;
            float v01 = acc[mt][nt][1] + b1v + x0.y;
            float v10 = acc[mt][nt][2] + b0 + x1v.x;
            float v11 = acc[mt][nt][3] + b1v + x1v.y;
            *(float2*)&X1[o0] = make_float2(v00, v01);
            *(float2*)&X1[o1] = make_float2(v10, v11);
            acc[mt][nt][0] = v00; acc[mt][nt][1] = v01;
            acc[mt][nt][2] = v10; acc[mt][nt][3] = v11;
            sa += v00 + v01;  ssa += v00*v00 + v01*v01;
            sb += v10 + v11;  ssb += v10*v10 + v11*v11;
        }
        #pragma unroll
        for (int o = 1; o <= 2; o <<= 1) {
            sa  += __shfl_xor_sync(0xffffffffu, sa,  o);
            ssa += __shfl_xor_sync(0xffffffffu, ssa, o);
            sb  += __shfl_xor_sync(0xffffffffu, sb,  o);
            ssb += __shfl_xor_sync(0xffffffffu, ssb, o);
        }
        if (tig == 0) {
            int lr = wrow * 32 + mt * 16 + gid;
            red_s [lr][wcol] = sa;  red_ss[lr][wcol] = ssa;
            red_s [lr + 8][wcol] = sb;  red_ss[lr + 8][wcol] = ssb;
        }
    }
    __syncthreads();

    #pragma unroll
    for (int mt = 0; mt < 2; mt++) {
        const int lr = wrow * 32 + mt * 16 + gid;
        const int r0 = bm + lr;
        const int r1 = r0 + 8;
        float mu0 = (red_s[lr][0] + red_s[lr][1]) * (1.0f/CDIM);
        float rs0 = rsqrtf((red_ss[lr][0] + red_ss[lr][1]) * (1.0f/CDIM)
                           - mu0*mu0 + 1e-5f);
        float mu1 = (red_s[lr+8][0] + red_s[lr+8][1]) * (1.0f/CDIM);
        float rs1 = rsqrtf((red_ss[lr+8][0] + red_ss[lr+8][1]) * (1.0f/CDIM)
                           - mu1*mu1 + 1e-5f);
        int w0 = (r0 >> 6) & 63, s0 = r0 & 63;
        int i0 = ((w0 >> 3) << 3) + (s0 >> 3), j0 = ((w0 & 7) << 3) + (s0 & 7);
        int d0 = (r0 & ~4095) | ((((i0 + SS) & 63) << 6) | ((j0 + SS) & 63));
        int w1 = (r1 >> 6) & 63, s1 = r1 & 63;
        int i1 = ((w1 >> 3) << 3) + (s1 >> 3), j1 = ((w1 & 7) << 3) + (s1 & 7);
        int d1 = (r1 & ~4095) | ((((i1 + SS) & 63) << 6) | ((j1 + SS) & 63));
        #pragma unroll
        for (int nt = 0; nt < 6; nt++) {
            const int col = wcol * 48 + nt * 8 + tig * 2;
            float gv0 = g2[col], gv1 = g2[col+1];
            float bv0 = b2[col], bv1 = b2[col+1];
            float h00 = (acc[mt][nt][0] - mu0) * rs0 * gv0 + bv0;
            float h01 = (acc[mt][nt][1] - mu0) * rs0 * gv1 + bv1;
            float h10 = (acc[mt][nt][2] - mu1) * rs1 * gv0 + bv0;
            float h11 = (acc[mt][nt][3] - mu1) * rs1 * gv1 + bv1;
            *(__nv_bfloat162*)&H2[(size_t)d0 * CDIM + col] =
                __nv_bfloat162(__float2bfloat16(h00), __float2bfloat16(h01));
            *(__nv_bfloat162*)&H2[(size_t)d1 * CDIM + col] =
                __nv_bfloat162(__float2bfloat16(h10), __float2bfloat16(h11));
        }
    }
}

// ---------------- fused MLP: FC1+GELU (smem) -> FC2 + residual --------------
#define MLP_SMEM (26624 + 26624 + 3*96*AROW*2)

__global__ void __launch_bounds__(256, 2)
mlp_fused(const bf16* __restrict__ h2, const float* __restrict__ fc1b,
          const float* __restrict__ fc2b, const float* __restrict__ x1,
          float* __restrict__ out)
{
    extern __shared__ __align__(16) char dyn[];
    bf16* As = (bf16*)dyn;
    bf16* Hs = (bf16*)(dyn + 26624);
    bf16* Wb = (bf16*)(dyn + 53248);

    const int t = threadIdx.x, warp = t >> 5, lane = t & 31;
    const int bm = blockIdx.x * 128;
    const int wrow = warp & 3, wcol = warp >> 2;
    const int gid = lane >> 2, tig = lane & 3;

    auto issueW1 = [&](int nc, int buf) {
        const bf16* src = g_wfc1 + (size_t)(nc * 96) * CDIM;
        bf16* Bd = Wb + buf * 96 * AROW;
        #pragma unroll
        for (int cid = t; cid < 1152; cid += 256) {
            int row = cid / 12, c = cid % 12;
            cp16(smem_u32(Bd + row * AROW + c * 8),
                 src + (size_t)row * CDIM + c * 8);
        }
        cp_commit();
    };
    auto issueW2 = [&](int nc, int buf) {
        const bf16* src = g_wfc2 + nc * 96;
        bf16* Bd = Wb + buf * 96 * AROW;
        #pragma unroll
        for (int cid = t; cid < 1152; cid += 256) {
            int row = cid / 12, c = cid % 12;
            cp16(smem_u32(Bd + row * AROW + c * 8),
                 src + (size_t)row * CH + c * 8);
        }
        cp_commit();
    };

    {
        #pragma unroll
        for (int cid = t; cid < 1536; cid += 256) {
            int row = cid / 12, c = cid % 12;
            cp16(smem_u32(As + row * AROW + c * 8),
                 h2 + (size_t)(bm + row) * CDIM + c * 8);
        }
        const bf16* src = g_wfc1;
        #pragma unroll
        for (int cid = t; cid < 1152; cid += 256) {
            int row = cid / 12, c = cid % 12;
            cp16(smem_u32(Wb + row * AROW + c * 8),
                 src + (size_t)row * CDIM + c * 8);
        }
        cp_commit();
    }
    issueW2(0, 1);
    issueW1(1, 2);

    float oacc[2][6][4];
    #pragma unroll
    for (int i = 0; i < 2; i++)
        #pragma unroll
        for (int j = 0; j < 6; j++)
            #pragma unroll
            for (int q = 0; q < 4; q++) oacc[i][j][q] = 0.0f;

    #pragma unroll
    for (int nc = 0; nc < 4; nc++) {
        if (nc == 3) cp_waitN<1>(); else cp_waitN<2>();
        __syncthreads();
        const bf16* W1b = Wb + ((2 * nc) % 3) * 96 * AROW;

        float facc[2][6][4];
        #pragma unroll
        for (int i = 0; i < 2; i++)
            #pragma unroll
            for (int j = 0; j < 6; j++)
                #pragma unroll
                for (int q = 0; q < 4; q++) facc[i][j][q] = 0.0f;

        #pragma unroll
        for (int ks = 0; ks < 96; ks += 16) {
            uint32_t af[2][4];
            #pragma unroll
            for (int mt = 0; mt < 2; mt++) {
                int row = wrow * 32 + mt * 16 + (lane & 15);
                int col = ks + ((lane >> 4) << 3);
                ldm_x4(af[mt][0], af[mt][1], af[mt][2], af[mt][3],
                       smem_u32(As + row * AROW + col));
            }
            uint32_t bfm[6][2];
            #pragma unroll
            for (int pr = 0; pr < 3; pr++) {
                int row = wcol * 48 + pr * 16 + (lane & 7) + ((lane >> 4) << 3);
                int col = ks + (((lane >> 3) & 1) << 3);
                uint32_t r0, r1, r2, r3;
                ldm_x4(r0, r1, r2, r3, smem_u32(W1b + row * AROW + col));
                bfm[pr*2  ][0] = r0; bfm[pr*2  ][1] = r1;
                bfm[pr*2+1][0] = r2; bfm[pr*2+1][1] = r3;
            }
            #pragma unroll
            for (int mt = 0; mt < 2; mt++)
                #pragma unroll
                for (int nt = 0; nt < 6; nt++)
                    mma_bf16(facc[mt][nt], af[mt], bfm[nt]);
        }

        #pragma unroll
        for (int mt = 0; mt < 2; mt++) {
            const int lr = wrow * 32 + mt * 16 + gid;
            #pragma unroll
            for (int nt = 0; nt < 6; nt++) {
                const int col = wcol * 48 + nt * 8 + tig * 2;
                const float b0 = fc1b[nc * 96 + col], b1v = fc1b[nc * 96 + col + 1];
                float v00 = gelu_f(facc[mt][nt][0] + b0);
                float v01 = gelu_f(facc[mt][nt][1] + b1v);
                float v10 = gelu_f(facc[mt][nt][2] + b0);
                float v11 = gelu_f(facc[mt][nt][3] + b1v);
                *(__nv_bfloat162*)(Hs + lr * AROW + col) =
                    __nv_bfloat162(__float2bfloat16(v00), __float2bfloat16(v01));
                *(__nv_bfloat162*)(Hs + (lr + 8) * AROW + col) =
                    __nv_bfloat162(__float2bfloat16(v10), __float2bfloat16(v11));
            }
        }
        if (nc == 3) cp_waitN<0>(); else cp_waitN<1>();
        __syncthreads();
        const bf16* W2b = Wb + ((2 * nc + 1) % 3) * 96 * AROW;

        #pragma unroll
        for (int ks = 0; ks < 96; ks += 16) {
            uint32_t af[2][4];
            #pragma unroll
            for (int mt = 0; mt < 2; mt++) {
                int row = wrow * 32 + mt * 16 + (lane & 15);
                int col = ks + ((lane >> 4) << 3);
                ldm_x4(af[mt][0], af[mt][1], af[mt][2], af[mt][3],
                       smem_u32(Hs + row * AROW + col));
            }
            uint32_t bfm[6][2];
            #pragma unroll
            for (int pr = 0; pr < 3; pr++) {
                int row = wcol * 48 + pr * 16 + (lane & 7) + ((lane >> 4) << 3);
                int col = ks + (((lane >> 3) & 1) << 3);
                uint32_t r0, r1, r2, r3;
                ldm_x4(r0, r1, r2, r3, smem_u32(W2b + row * AROW + col));
                bfm[pr*2  ][0] = r0; bfm[pr*2  ][1] = r1;
                bfm[pr*2+1][0] = r2; bfm[pr*2+1][1] = r3;
            }
            #pragma unroll
            for (int mt = 0; mt < 2; mt++)
                #pragma unroll
                for (int nt = 0; nt < 6; nt++)
                    mma_bf16(oacc[mt][nt], af[mt], bfm[nt]);
        }
        __syncthreads();

        if (nc == 0) { issueW2(1, 0); issueW1(2, 1); }
        else if (nc == 1) { issueW2(2, 2); issueW1(3, 0); }
        else if (nc == 2) { issueW2(3, 1); }
    }

    #pragma unroll
    for (int mt = 0; mt < 2; mt++) {
        const int r0 = bm + wrow * 32 + mt * 16 + gid;
        const int r1 = r0 + 8;
        #pragma unroll
        for (int nt = 0; nt < 6; nt++) {
            const int col = wcol * 48 + nt * 8 + tig * 2;
            const float b0 = fc2b[col], b1v = fc2b[col + 1];
            float2 x0 = *(const float2*)&x1[(size_t)r0 * CDIM + col];
            float2 x1v = *(const float2*)&x1[(size_t)r1 * CDIM + col];
            *(float2*)&out[(size_t)r0 * CDIM + col] =
                make_float2(oacc[mt][nt][0] + b0 + x0.x,
                            oacc[mt][nt][1] + b1v + x0.y);
            *(float2*)&out[(size_t)r1 * CDIM + col] =
                make_float2(oacc[mt][nt][2] + b0 + x1v.x,
                            oacc[mt][nt][3] + b1v + x1v.y);
        }
    }
}

// ---------------- tensor-core windowed attention (V via ldmatrix.trans) -----
#define ATTN_SMEM 37888

__global__ void __launch_bounds__(256)
attn_tc(const bf16* __restrict__ qkv, bf16* __restrict__ o)
{
    extern __shared__ __align__(16) char sm_[];
    bf16 (*S)[296] = (bf16(*)[296])sm_;

    const int win  = blockIdx.x;
    const int t    = threadIdx.x;
    const int warp = t >> 5, lane = t & 31;
    const int head = warp >> 1, mh = warp & 1;
    const int gid  = lane >> 2, tig = lane & 3;

    const bf16* wq = qkv + (size_t)win * 64 * C3;

    #pragma unroll
    for (int i = 0; i < 9; i++) {
        int cid = t + i * 256;
        int row = cid / 36, c = cid % 36;
        cp16(smem_u32(&S[row][c * 8]), wq + (size_t)row * C3 + c * 8);
    }
    cp_commit();
    cp_wait0();
    __syncthreads();

    const int qc = head * HD;
    const int kc = 96 + head * HD;
    const int vc = 192 + head * HD;

    // Q fragments via ldmatrix
    uint32_t aq[2][2][4];
    #pragma unroll
    for (int mt = 0; mt < 2; mt++) {
        #pragma unroll
        for (int kt = 0; kt < 2; kt++) {
            int row = mh * 32 + mt * 16 + (lane & 15);
            int col = qc + kt * 16 + ((lane >> 4) << 3);
            ldm_x4(aq[mt][kt][0], aq[mt][kt][1], aq[mt][kt][2], aq[mt][kt][3],
                   smem_u32(&S[row][col]));
        }
        aq[mt][1][2] = 0u; aq[mt][1][3] = 0u;   // dims 24..31 invalid
    }
    // K fragments via ldmatrix
    uint32_t bk[8][2][2];
    #pragma unroll
    for (int np = 0; np < 4; np++) {
        #pragma unroll
        for (int kt = 0; kt < 2; kt++) {
            int row = np * 16 + (lane & 7) + ((lane >> 4) << 3);
            int col = kc + kt * 16 + (((lane >> 3) & 1) << 3);
            uint32_t r0, r1, r2, r3;
            ldm_x4(r0, r1, r2, r3, smem_u32(&S[row][col]));
            bk[np*2  ][kt][0] = r0; bk[np*2  ][kt][1] = (kt == 0) ? r1 : 0u;
            bk[np*2+1][kt][0] = r2; bk[np*2+1][kt][1] = (kt == 0) ? r3 : 0u;
        }
    }

    // ---- S = Q @ K^T ----
    float acc[2][8][4];
    #pragma unroll
    for (int mt = 0; mt < 2; mt++)
        #pragma unroll
        for (int nt = 0; nt < 8; nt++)
            #pragma unroll
            for (int q = 0; q < 4; q++) acc[mt][nt][q] = 0.0f;

    #pragma unroll
    for (int mt = 0; mt < 2; mt++)
        #pragma unroll
        for (int nt = 0; nt < 8; nt++)
            #pragma unroll
            for (int kt = 0; kt < 2; kt++)
                mma_bf16(acc[mt][nt], aq[mt][kt], bk[nt][kt]);

    const int wimg = win & 63;
    const int cls = (((wimg >> 3) == 7) ? 2 : 0) | (((wimg & 7) == 7) ? 1 : 0);
    const float* bt = g_bias_exp + cls * 16384;

    const float K1 = 0.2944888985f;   // 24^-0.5 * log2(e)

    // ---- exp + row-sum accumulation; pack P to bf16x2 ----
    uint32_t p01[2][8], p23[2][8];
    float rs0[2] = {0.f, 0.f}, rs1[2] = {0.f, 0.f};
    #pragma unroll
    for (int mt = 0; mt < 2; mt++) {
        #pragma unroll
        for (int nt = 0; nt < 8; nt++) {
            const float4 bb = *(const float4*)&bt[
                (((((head * 2 + mh) * 2 + mt) * 8 + nt) * 32 + lane) << 2)];
            float e00 = exp2_poly(acc[mt][nt][0] * K1 + bb.x);
            float e01 = exp2_poly(acc[mt][nt][1] * K1 + bb.y);
            float e10 = exp2_poly(acc[mt][nt][2] * K1 + bb.z);
            float e11 = exp2_poly(acc[mt][nt][3] * K1 + bb.w);
            rs0[mt] += e00 + e01;
            rs1[mt] += e10 + e11;
            __nv_bfloat162 h01(__float2bfloat16(e00), __float2bfloat16(e01));
            __nv_bfloat162 h23(__float2bfloat16(e10), __float2bfloat16(e11));
            p01[mt][nt] = *(uint32_t*)&h01;
            p23[mt][nt] = *(uint32_t*)&h23;
        }
    }
    // reduce row sums across the quad (tig lanes)
    #pragma unroll
    for (int mt = 0; mt < 2; mt++) {
        #pragma unroll
        for (int o = 1; o <= 2; o <<= 1) {
            rs0[mt] += __shfl_xor_sync(0xffffffffu, rs0[mt], o);
            rs1[mt] += __shfl_xor_sync(0xffffffffu, rs1[mt], o);
        }
    }

    // ---- O = P @ V, V B-fragments via ldmatrix.trans from S ----
    float ao[2][3][4];
    #pragma unroll
    for (int mt = 0; mt < 2; mt++)
        #pragma unroll
        for (int nv = 0; nv < 3; nv++)
            #pragma unroll
            for (int q = 0; q < 4; q++) ao[mt][nv][q] = 0.0f;

    #pragma unroll
    for (int kt = 0; kt < 4; kt++) {
        // V[tok][d] tiles, transposed -> B frags (n=d, k=tok)
        int row = kt * 16 + (lane & 7) + (((lane >> 3) & 1) << 3);
        uint32_t bv[3][2];
        {
            uint32_t r0, r1, r2, r3;
            int col = vc + ((lane >> 4) << 3);
            ldm_x4_t(r0, r1, r2, r3, smem_u32(&S[row][col]));
            bv[0][0] = r0; bv[0][1] = r1;   // d 0..7
            bv[1][0] = r2; bv[1][1] = r3;   // d 8..15
        }
        {
            uint32_t r0, r1, r2, r3;
            int col = vc + 16 + ((lane >> 4) << 3);   // d 16..23 (+ padding tiles)
            ldm_x4_t(r0, r1, r2, r3, smem_u32(&S[row][col]));
            bv[2][0] = r0; bv[2][1] = r1;
        }
        #pragma unroll
        for (int mt = 0; mt < 2; mt++) {
            uint32_t ap[4] = { p01[mt][2*kt], p23[mt][2*kt],
                               p01[mt][2*kt+1], p23[mt][2*kt+1] };
            #pragma unroll
            for (int nv = 0; nv < 3; nv++)
                mma_bf16(ao[mt][nv], ap, bv[nv]);
        }
    }

    // ---- normalize & store ----
    #pragma unroll
    for (int mt = 0; mt < 2; mt++) {
        float inv0 = __fdividef(1.0f, rs0[mt]);
        float inv1 = __fdividef(1.0f, rs1[mt]);
        int row0 = win * 64 + mh * 32 + mt * 16 + gid;
        #pragma unroll
        for (int nv = 0; nv < 3; nv++) {
            int col = head * HD + nv * 8 + tig * 2;
            *(__nv_bfloat162*)&o[(size_t)row0 * CDIM + col] =
                __nv_bfloat162(__float2bfloat16(ao[mt][nv][0] * inv0),
                               __float2bfloat16(ao[mt][nv][1] * inv0));
            *(__nv_bfloat162*)&o[(size_t)(row0 + 8) * CDIM + col] =
                __nv_bfloat162(__float2bfloat16(ao[mt][nv][2] * inv1),
                               __float2bfloat16(ao[mt][nv][3] * inv1));
        }
    }
}

// ---------------- launch ----------------------------------------------------
extern "C" void kernel_launch(void* const* d_in, const int* in_sizes, int n_in,
                              void* d_out, int out_size)
{
    const float* x       = (const float*)d_in[0];
    const float* norm1_g = (const float*)d_in[1];
    const float* norm1_b = (const float*)d_in[2];
    const float* qkv_w   = (const float*)d_in[3];
    const float* qkv_b   = (const float*)d_in[4];
    const float* rpb     = (const float*)d_in[5];
    const float* proj_w  = (const float*)d_in[6];
    const float* proj_b  = (const float*)d_in[7];
    const float* norm2_g = (const float*)d_in[8];
    const float* norm2_b = (const float*)d_in[9];
    const float* fc1_w   = (const float*)d_in[10];
    const float* fc1_b   = (const float*)d_in[11];
    const float* fc2_w   = (const float*)d_in[12];
    const float* fc2_b   = (const float*)d_in[13];
    float* out = (float*)d_out;

    bf16 *qkv_p, *o_p, *h2_p;
    bf16 *wqkv_p, *wproj_p;
    float *x1_p;
    cudaGetSymbolAddress((void**)&qkv_p,  g_qkv);
    cudaGetSymbolAddress((void**)&o_p,    g_o);
    cudaGetSymbolAddress((void**)&x1_p,   g_x1);
    cudaGetSymbolAddress((void**)&h2_p,   g_h2);
    cudaGetSymbolAddress((void**)&wqkv_p, g_wqkv);
    cudaGetSymbolAddress((void**)&wproj_p,g_wproj);

    cudaFuncSetAttribute(attn_tc, cudaFuncAttributeMaxDynamicSharedMemorySize,
                         ATTN_SMEM);
    cudaFuncSetAttribute(qkv_nloop,
                         cudaFuncAttributeMaxDynamicSharedMemorySize, NLOOP_SMEM);
    cudaFuncSetAttribute(mlp_fused,
                         cudaFuncAttributeMaxDynamicSharedMemorySize, MLP_SMEM);

    conv_weights<<<(CH*CDIM + 255)/256, 256>>>(qkv_w, proj_w, fc1_w, fc2_w);
    build_bias<<<256, 256>>>(rpb);

    // LN1 + shift/window + QKV
    qkv_nloop<<<TOKENS/128, 256, NLOOP_SMEM>>>(
        x, wqkv_p, qkv_b, norm1_g, norm1_b, qkv_p);

    // windowed attention
    attn_tc<<<NWIN, 256, ATTN_SMEM>>>(qkv_p, o_p);

    // proj + window-reverse + residual + LN2 -> x1 (fp32), h2 (bf16)
    proj_ln2<<<TOKENS/128, 256>>>(o_p, wproj_p, proj_b, x,
                                  norm2_g, norm2_b, x1_p, h2_p);

    // fused FC1 + GELU + FC2 + residual -> out
    mlp_fused<<<TOKENS/128, 256, MLP_SMEM>>>(h2_p, fc1_b, fc2_b, x1_p, out);
}

// round 16
// speedup vs baseline: 1.1197x; 1.0192x over previous
#include <cuda_runtime.h>
#include <cuda_bf16.h>
#include <cuda_fp16.h>
#include <cstdint>
#include <cstddef>

// ---------------- static problem sizes -------------------------------------
#define SS      4
#define NH      4
#define CDIM    96
#define HD      24
#define NWIN    4096
#define TOKENS  262144
#define C3      288
#define CH      384

typedef __nv_bfloat16 bf16;

// ---------------- scratch ---------------------------------------------------
__device__ bf16  g_qkv[(size_t)TOKENS * C3];
__device__ bf16  g_o  [(size_t)TOKENS * CDIM];
__device__ float g_x1 [(size_t)TOKENS * CDIM];
__device__ bf16  g_h2 [(size_t)TOKENS * CDIM];
__device__ bf16  g_wqkv[C3 * CDIM];
__device__ bf16  g_wproj[CDIM * CDIM];
__device__ bf16  g_wfc1[CH * CDIM];
__device__ bf16  g_wfc2[CDIM * CH];
__device__ float g_bias_exp[4 * 16384];

// ---------------- asm helpers ----------------------------------------------
__device__ __forceinline__ uint32_t smem_u32(const void* p) {
    return (uint32_t)__cvta_generic_to_shared(p);
}
__device__ __forceinline__ void ldm_x4(uint32_t& r0, uint32_t& r1, uint32_t& r2,
                                       uint32_t& r3, uint32_t addr) {
    asm volatile("ldmatrix.sync.aligned.m8n8.x4.shared.b16 {%0,%1,%2,%3}, [%4];\n"
                 : "=r"(r0), "=r"(r1), "=r"(r2), "=r"(r3) : "r"(addr));
}
__device__ __forceinline__ void ldm_x4_t(uint32_t& r0, uint32_t& r1, uint32_t& r2,
                                         uint32_t& r3, uint32_t addr) {
    asm volatile("ldmatrix.sync.aligned.m8n8.x4.trans.shared.b16 {%0,%1,%2,%3}, [%4];\n"
                 : "=r"(r0), "=r"(r1), "=r"(r2), "=r"(r3) : "r"(addr));
}
__device__ __forceinline__ void mma_bf16(float c[4], const uint32_t a[4],
                                         const uint32_t b[2]) {
    asm volatile(
        "mma.sync.aligned.m16n8k16.row.col.f32.bf16.bf16.f32 "
        "{%0,%1,%2,%3},{%4,%5,%6,%7},{%8,%9},{%0,%1,%2,%3};\n"
        : "+f"(c[0]), "+f"(c[1]), "+f"(c[2]), "+f"(c[3])
        : "r"(a[0]), "r"(a[1]), "r"(a[2]), "r"(a[3]), "r"(b[0]), "r"(b[1]));
}
__device__ __forceinline__ void cp16(uint32_t dst, const void* src) {
    asm volatile("cp.async.ca.shared.global [%0], [%1], 16;\n"
                 :: "r"(dst), "l"(src));
}
__device__ __forceinline__ void cp_commit() { asm volatile("cp.async.commit_group;\n"); }
__device__ __forceinline__ void cp_wait0() { asm volatile("cp.async.wait_group 0;\n"); }
__device__ __forceinline__ void cp_wait1() { asm volatile("cp.async.wait_group 1;\n"); }
template<int N>
__device__ __forceinline__ void cp_waitN() {
    asm volatile("cp.async.wait_group %0;\n" :: "n"(N));
}

__device__ __forceinline__ float exp2_poly(float z) {
    z = fmaxf(z, -100.0f);
    float t = z + 12582912.0f;
    int   n = __float_as_int(t) - 0x4B400000;
    float f = z - (t - 12582912.0f);
    float p = 0.009618129107f;
    p = p * f + 0.05550410866f;
    p = p * f + 0.2402265069f;
    p = p * f + 0.69314718056f;
    p = p * f + 1.0f;
    return p * __int_as_float((n + 127) << 23);
}
__device__ __forceinline__ float gelu_f(float v) {
    return 0.5f * v * (1.0f + erff(v * 0.70710678118654752f));
}

// ---------------- weight conversion -----------------------------------------
__global__ void conv_weights(const float* __restrict__ a, const float* __restrict__ b,
                             const float* __restrict__ c, const float* __restrict__ d)
{
    int i = blockIdx.x * 256 + threadIdx.x;
    if (i < C3 * CDIM)   g_wqkv[i]  = __float2bfloat16(a[i]);
    if (i < CDIM * CDIM) g_wproj[i] = __float2bfloat16(b[i]);
    if (i < CH * CDIM) { g_wfc1[i]  = __float2bfloat16(c[i]);
                         g_wfc2[i]  = __float2bfloat16(d[i]); }
}

// ---------------- bias+mask expansion (4 window classes) --------------------
__global__ void build_bias(const float* __restrict__ rpb)
{
    int idx = blockIdx.x * 256 + threadIdx.x;
    int cls = idx >> 14;
    int e   = idx & 16383;
    int q    = e & 3;
    int lane = (e >> 2) & 31;
    int nt   = (e >> 7) & 7;
    int mt   = (e >> 10) & 1;
    int mh   = (e >> 11) & 1;
    int head = (e >> 12) & 3;
    int gid = lane >> 2, tig = lane & 3;
    int n = mh*32 + mt*16 + gid + ((q >> 1) << 3);
    int m = nt*8 + tig*2 + (q & 1);
    int ni = n >> 3, nj = n & 7, mi = m >> 3, mj = m & 7;
    int ridx = (ni - mi + 7) * 15 + (nj - mj + 7);
    int wi7 = cls >> 1, wj7 = cls & 1;
    int rq = (wi7 ? ((ni < 4) ? 1 : 2) : 0) * 3 + (wj7 ? ((nj < 4) ? 1 : 2) : 0);
    int rk = (wi7 ? ((mi < 4) ? 1 : 2) : 0) * 3 + (wj7 ? ((mj < 4) ? 1 : 2) : 0);
    float mask = (rq != rk) ? -144.269504089f : 0.0f;
    g_bias_exp[idx] = rpb[ridx * NH + head] * 1.4426950408889634f + mask;
}

// ---------------- vectorized LN row helper ----------------------------------
__device__ __forceinline__ void ln_row_v4(const float* __restrict__ xr,
                                          const float* __restrict__ g,
                                          const float* __restrict__ b,
                                          bf16* __restrict__ orow, int lane)
{
    float4 v = make_float4(0.f, 0.f, 0.f, 0.f);
    if (lane < 24) v = *(const float4*)(xr + lane * 4);
    float s  = v.x + v.y + v.z + v.w;
    float ss = v.x*v.x + v.y*v.y + v.z*v.z + v.w*v.w;
    #pragma unroll
    for (int o = 16; o; o >>= 1) {
        s  += __shfl_xor_sync(0xffffffffu, s,  o);
        ss += __shfl_xor_sync(0xffffffffu, ss, o);
    }
    float mu = s * (1.0f/CDIM);
    float rs = rsqrtf(ss * (1.0f/CDIM) - mu*mu + 1e-5f);
    if (lane < 24) {
        float4 gv = *(const float4*)(g + lane * 4);
        float4 bv = *(const float4*)(b + lane * 4);
        __nv_bfloat162 lo((__nv_bfloat16)((v.x - mu) * rs * gv.x + bv.x),
                          (__nv_bfloat16)((v.y - mu) * rs * gv.y + bv.y));
        __nv_bfloat162 hi((__nv_bfloat16)((v.z - mu) * rs * gv.z + bv.z),
                          (__nv_bfloat16)((v.w - mu) * rs * gv.w + bv.w));
        uint2 pk;
        pk.x = *(uint32_t*)&lo;
        pk.y = *(uint32_t*)&hi;
        *(uint2*)(orow + lane * 4) = pk;
    }
}

// ---------------- QKV: LN1 + shift/window + N-loop GEMM ---------------------
#define AROW 104
#define NLOOP_SMEM (128*AROW*2 + 2*96*AROW*2)

__global__ void __launch_bounds__(256, 3)
qkv_nloop(const float* __restrict__ x, const bf16* __restrict__ W,
          const float* __restrict__ bias,
          const float* __restrict__ g1, const float* __restrict__ b1,
          bf16* __restrict__ Cout)
{
    extern __shared__ __align__(16) char dyn[];
    bf16* As = (bf16*)dyn;
    bf16* Bs = (bf16*)(dyn + 128*AROW*2);

    const int t = threadIdx.x, warp = t >> 5, lane = t & 31;
    const int bm = blockIdx.x * 128;
    const int wrow = warp & 3, wcol = warp >> 2;
    const int gid = lane >> 2, tig = lane & 3;

    auto issueB = [&](int nc, int buf) {
        const bf16* Wb = W + (size_t)(nc * 96) * CDIM;
        bf16* Bd = Bs + buf * 96 * AROW;
        #pragma unroll
        for (int cid = t; cid < 1152; cid += 256) {
            int row = cid / 12, c = cid % 12;
            cp16(smem_u32(Bd + row * AROW + c * 8),
                 Wb + (size_t)row * CDIM + c * 8);
        }
        cp_commit();
    };

    issueB(0, 0);

    #pragma unroll
    for (int it = 0; it < 16; it++) {
        int r  = it * 8 + warp;
        int wr = bm + r;
        int w = (wr >> 6) & 63, s = wr & 63;
        int i0 = ((w >> 3) << 3) + (s >> 3), j0 = ((w & 7) << 3) + (s & 7);
        int src = (wr & ~4095) | ((((i0 + SS) & 63) << 6) | ((j0 + SS) & 63));
        ln_row_v4(x + (size_t)src * CDIM, g1, b1, As + r * AROW, lane);
    }

    #pragma unroll
    for (int nc = 0; nc < 3; nc++) {
        if (nc + 1 < 3) { issueB(nc + 1, (nc + 1) & 1); cp_wait1(); }
        else            { cp_wait0(); }
        __syncthreads();
        const bf16* Bb = Bs + (nc & 1) * 96 * AROW;

        float acc[2][6][4];
        #pragma unroll
        for (int i = 0; i < 2; i++)
            #pragma unroll
            for (int j = 0; j < 6; j++)
                #pragma unroll
                for (int q = 0; q < 4; q++) acc[i][j][q] = 0.0f;

        #pragma unroll
        for (int ks = 0; ks < 96; ks += 16) {
            uint32_t af[2][4];
            #pragma unroll
            for (int mt = 0; mt < 2; mt++) {
                int row = wrow * 32 + mt * 16 + (lane & 15);
                int col = ks + ((lane >> 4) << 3);
                ldm_x4(af[mt][0], af[mt][1], af[mt][2], af[mt][3],
                       smem_u32(As + row * AROW + col));
            }
            uint32_t bfm[6][2];
            #pragma unroll
            for (int pr = 0; pr < 3; pr++) {
                int row = wcol * 48 + pr * 16 + (lane & 7) + ((lane >> 4) << 3);
                int col = ks + (((lane >> 3) & 1) << 3);
                uint32_t r0, r1, r2, r3;
                ldm_x4(r0, r1, r2, r3, smem_u32(Bb + row * AROW + col));
                bfm[pr*2  ][0] = r0; bfm[pr*2  ][1] = r1;
                bfm[pr*2+1][0] = r2; bfm[pr*2+1][1] = r3;
            }
            #pragma unroll
            for (int mt = 0; mt < 2; mt++)
                #pragma unroll
                for (int nt = 0; nt < 6; nt++)
                    mma_bf16(acc[mt][nt], af[mt], bfm[nt]);
        }

        #pragma unroll
        for (int mt = 0; mt < 2; mt++) {
            const int r0 = bm + wrow * 32 + mt * 16 + gid;
            const int r1 = r0 + 8;
            #pragma unroll
            for (int nt = 0; nt < 6; nt++) {
                const int col = nc * 96 + wcol * 48 + nt * 8 + tig * 2;
                const float b0 = bias[col], b1v = bias[col + 1];
                *(__nv_bfloat162*)&Cout[(size_t)r0 * C3 + col] =
                    __nv_bfloat162(__float2bfloat16(acc[mt][nt][0] + b0),
                                   __float2bfloat16(acc[mt][nt][1] + b1v));
                *(__nv_bfloat162*)&Cout[(size_t)r1 * C3 + col] =
                    __nv_bfloat162(__float2bfloat16(acc[mt][nt][2] + b0),
                                   __float2bfloat16(acc[mt][nt][3] + b1v));
            }
        }
        __syncthreads();
    }
}

// ---------------- proj GEMM + window-reverse + residual + LN2 ---------------
#define SROW 40
__global__ void __launch_bounds__(256, 3)
proj_ln2(const bf16* __restrict__ A, const bf16* __restrict__ W,
         const float* __restrict__ bias, const float* __restrict__ xres,
         const float* __restrict__ g2, const float* __restrict__ b2,
         float* __restrict__ X1, bf16* __restrict__ H2)
{
    __shared__ bf16 As[2][128][SROW];
    __shared__ bf16 Bs[2][96][SROW];
    __shared__ float red_s[128][2];
    __shared__ float red_ss[128][2];

    const int t = threadIdx.x;
    const int bm = blockIdx.x * 128;
    const int warp = t >> 5, lane = t & 31;
    const int wrow = warp & 3, wcol = warp >> 2;
    const int gid = lane >> 2, tig = lane & 3;

    float acc[2][6][4];
    #pragma unroll
    for (int i = 0; i < 2; i++)
        #pragma unroll
        for (int j = 0; j < 6; j++)
            #pragma unroll
            for (int q = 0; q < 4; q++) acc[i][j][q] = 0.0f;

    auto issue = [&](int kt, int buf) {
        const int k0 = kt << 5;
        #pragma unroll
        for (int c = 0; c < 2; c++) {
            int cid = t + c * 256;
            int row = cid >> 2, cc = cid & 3;
            cp16(smem_u32(&As[buf][row][cc * 8]),
                 A + (size_t)(bm + row) * CDIM + k0 + cc * 8);
        }
        {
            int row = t >> 2, cc = t & 3;
            cp16(smem_u32(&Bs[buf][row][cc * 8]),
                 W + (size_t)row * CDIM + k0 + cc * 8);
        }
        if (t < 128) {
            int cid = 256 + t;
            int row = cid >> 2, cc = cid & 3;
            cp16(smem_u32(&Bs[buf][row][cc * 8]),
                 W + (size_t)row * CDIM + k0 + cc * 8);
        }
        cp_commit();
    };

    issue(0, 0);
    for (int kt = 0; kt < 3; kt++) {
        cp_wait0();
        __syncthreads();
        if (kt + 1 < 3) issue(kt + 1, (kt + 1) & 1);
        const int buf = kt & 1;
        #pragma unroll
        for (int ks = 0; ks < 32; ks += 16) {
            uint32_t af[2][4];
            #pragma unroll
            for (int mt = 0; mt < 2; mt++) {
                int row = wrow * 32 + mt * 16 + (lane & 15);
                int col = ks + ((lane >> 4) << 3);
                ldm_x4(af[mt][0], af[mt][1], af[mt][2], af[mt][3],
                       smem_u32(&As[buf][row][col]));
            }
            uint32_t bfm[6][2];
            #pragma unroll
            for (int pr = 0; pr < 3; pr++) {
                int row = wcol * 48 + pr * 16 + (lane & 7) + ((lane >> 4) << 3);
                int col = ks + (((lane >> 3) & 1) << 3);
                uint32_t r0, r1, r2, r3;
                ldm_x4(r0, r1, r2, r3, smem_u32(&Bs[buf][row][col]));
                bfm[pr*2  ][0] = r0; bfm[pr*2  ][1] = r1;
                bfm[pr*2+1][0] = r2; bfm[pr*2+1][1] = r3;
            }
            #pragma unroll
            for (int mt = 0; mt < 2; mt++)
                #pragma unroll
                for (int nt = 0; nt < 6; nt++)
                    mma_bf16(acc[mt][nt], af[mt], bfm[nt]);
        }
        __syncthreads();
    }

    #pragma unroll
    for (int mt = 0; mt < 2; mt++) {
        const int r0 = bm + wrow * 32 + mt * 16 + gid;
        const int r1 = r0 + 8;
        int w0 = (r0 >> 6) & 63, s0 = r0 & 63;
        int i0 = ((w0 >> 3) << 3) + (s0 >> 3), j0 = ((w0 & 7) << 3) + (s0 & 7);
        int d0 = (r0 & ~4095) | ((((i0 + SS) & 63) << 6) | ((j0 + SS) & 63));
        int w1 = (r1 >> 6) & 63, s1 = r1 & 63;
        int i1 = ((w1 >> 3) << 3) + (s1 >> 3), j1 = ((w1 & 7) << 3) + (s1 & 7);
        int d1 = (r1 & ~4095) | ((((i1 + SS) & 63) << 6) | ((j1 + SS) & 63));

        float sa = 0.f, ssa = 0.f, sb = 0.f, ssb = 0.f;
        #pragma unroll
        for (int nt = 0; nt < 6; nt++) {
            const int col = wcol * 48 + nt * 8 + tig * 2;
            const float b0 = bias[col], b1v = bias[col + 1];
            size_t o0 = (size_t)d0 * CDIM + col;
            size_t o1 = (size_t)d1 * CDIM + col;
            float2 x0 = *(const float2*)&xres[o0];
            float2 x1v = *(const float2*)&xres[o1];
            float v00 = acc[mt][nt][0] + b0 + x0.x;
            float v01 = acc[mt][nt][1] + b1v + x0.y;
            float v10 = acc[mt][nt][2] + b0 + x1v.x;
            float v11 = acc[mt][nt][3] + b1v + x1v.y;
            *(float2*)&X1[o0] = make_float2(v00, v01);
            *(float2*)&X1[o1] = make_float2(v10, v11);
            acc[mt][nt][0] = v00; acc[mt][nt][1] = v01;
            acc[mt][nt][2] = v10; acc[mt][nt][3] = v11;
            sa += v00 + v01;  ssa += v00*v00 + v01*v01;
            sb += v10 + v11;  ssb += v10*v10 + v11*v11;
        }
        #pragma unroll
        for (int o = 1; o <= 2; o <<= 1) {
            sa  += __shfl_xor_sync(0xffffffffu, sa,  o);
            ssa += __shfl_xor_sync(0xffffffffu, ssa, o);
            sb  += __shfl_xor_sync(0xffffffffu, sb,  o);
            ssb += __shfl_xor_sync(0xffffffffu, ssb, o);
        }
        if (tig == 0) {
            int lr = wrow * 32 + mt * 16 + gid;
            red_s [lr][wcol] = sa;  red_ss[lr][wcol] = ssa;
            red_s [lr + 8][wcol] = sb;  red_ss[lr + 8][wcol] = ssb;
        }
    }
    __syncthreads();

    #pragma unroll
    for (int mt = 0; mt < 2; mt++) {
        const int lr = wrow * 32 + mt * 16 + gid;
        const int r0 = bm + lr;
        const int r1 = r0 + 8;
        float mu0 = (red_s[lr][0] + red_s[lr][1]) * (1.0f/CDIM);
        float rs0 = rsqrtf((red_ss[lr][0] + red_ss[lr][1]) * (1.0f/CDIM)
                           - mu0*mu0 + 1e-5f);
        float mu1 = (red_s[lr+8][0] + red_s[lr+8][1]) * (1.0f/CDIM);
        float rs1 = rsqrtf((red_ss[lr+8][0] + red_ss[lr+8][1]) * (1.0f/CDIM)
                           - mu1*mu1 + 1e-5f);
        int w0 = (r0 >> 6) & 63, s0 = r0 & 63;
        int i0 = ((w0 >> 3) << 3) + (s0 >> 3), j0 = ((w0 & 7) << 3) + (s0 & 7);
        int d0 = (r0 & ~4095) | ((((i0 + SS) & 63) << 6) | ((j0 + SS) & 63));
        int w1 = (r1 >> 6) & 63, s1 = r1 & 63;
        int i1 = ((w1 >> 3) << 3) + (s1 >> 3), j1 = ((w1 & 7) << 3) + (s1 & 7);
        int d1 = (r1 & ~4095) | ((((i1 + SS) & 63) << 6) | ((j1 + SS) & 63));
        #pragma unroll
        for (int nt = 0; nt < 6; nt++) {
            const int col = wcol * 48 + nt * 8 + tig * 2;
            float gv0 = g2[col], gv1 = g2[col+1];
            float bv0 = b2[col], bv1 = b2[col+1];
            float h00 = (acc[mt][nt][0] - mu0) * rs0 * gv0 + bv0;
            float h01 = (acc[mt][nt][1] - mu0) * rs0 * gv1 + bv1;
            float h10 = (acc[mt][nt][2] - mu1) * rs1 * gv0 + bv0;
            float h11 = (acc[mt][nt][3] - mu1) * rs1 * gv1 + bv1;
            *(__nv_bfloat162*)&H2[(size_t)d0 * CDIM + col] =
                __nv_bfloat162(__float2bfloat16(h00), __float2bfloat16(h01));
            *(__nv_bfloat162*)&H2[(size_t)d1 * CDIM + col] =
                __nv_bfloat162(__float2bfloat16(h10), __float2bfloat16(h11));
        }
    }
}

// ---------------- fused MLP: FC1+GELU (registers) -> FC2 + residual ---------
// Warp tile: 16 rows x 96 cols for both FC1 and FC2. H never touches smem:
// FC1 C-fragments are GELU'd and repacked in-register as FC2 A-fragments.
#define MLP_SMEM (26624 + 3*96*AROW*2)

__global__ void __launch_bounds__(256, 2)
mlp_fused(const bf16* __restrict__ h2, const float* __restrict__ fc1b,
          const float* __restrict__ fc2b, const float* __restrict__ x1,
          float* __restrict__ out)
{
    extern __shared__ __align__(16) char dyn[];
    bf16* As = (bf16*)dyn;                 // [128][104]
    bf16* Wb = (bf16*)(dyn + 26624);       // [3][96][104]

    const int t = threadIdx.x, warp = t >> 5, lane = t & 31;
    const int bm = blockIdx.x * 128;
    const int gid = lane >> 2, tig = lane & 3;

    auto issueW1 = [&](int nc, int buf) {
        const bf16* src = g_wfc1 + (size_t)(nc * 96) * CDIM;
        bf16* Bd = Wb + buf * 96 * AROW;
        #pragma unroll
        for (int cid = t; cid < 1152; cid += 256) {
            int row = cid / 12, c = cid % 12;
            cp16(smem_u32(Bd + row * AROW + c * 8),
                 src + (size_t)row * CDIM + c * 8);
        }
        cp_commit();
    };
    auto issueW2 = [&](int nc, int buf) {
        const bf16* src = g_wfc2 + nc * 96;
        bf16* Bd = Wb + buf * 96 * AROW;
        #pragma unroll
        for (int cid = t; cid < 1152; cid += 256) {
            int row = cid / 12, c = cid % 12;
            cp16(smem_u32(Bd + row * AROW + c * 8),
                 src + (size_t)row * CH + c * 8);
        }
        cp_commit();
    };

    // G0: A tile (h2) + W1[0] -> buf 0
    {
        #pragma unroll
        for (int cid = t; cid < 1536; cid += 256) {
            int row = cid / 12, c = cid % 12;
            cp16(smem_u32(As + row * AROW + c * 8),
                 h2 + (size_t)(bm + row) * CDIM + c * 8);
        }
        const bf16* src = g_wfc1;
        #pragma unroll
        for (int cid = t; cid < 1152; cid += 256) {
            int row = cid / 12, c = cid % 12;
            cp16(smem_u32(Wb + row * AROW + c * 8),
                 src + (size_t)row * CDIM + c * 8);
        }
        cp_commit();
    }
    issueW2(0, 1);   // G1
    issueW1(1, 2);   // G2

    float oacc[12][4];
    #pragma unroll
    for (int j = 0; j < 12; j++)
        #pragma unroll
        for (int q = 0; q < 4; q++) oacc[j][q] = 0.0f;

    #pragma unroll
    for (int nc = 0; nc < 4; nc++) {
        // wait W1[nc] and W2[nc] (issued >=1 chunk ahead)
        if (nc == 3) cp_waitN<0>(); else cp_waitN<1>();
        __syncthreads();
        const bf16* W1b = Wb + ((2 * nc) % 3) * 96 * AROW;
        const bf16* W2b = Wb + ((2 * nc + 1) % 3) * 96 * AROW;

        // ---- FC1 chunk: facc(16x96) = As(16x96) @ W1[nc]^T ----
        float facc[12][4];
        #pragma unroll
        for (int j = 0; j < 12; j++)
            #pragma unroll
            for (int q = 0; q < 4; q++) facc[j][q] = 0.0f;

        #pragma unroll
        for (int ks = 0; ks < 96; ks += 16) {
            uint32_t af[4];
            {
                int row = warp * 16 + (lane & 15);
                int col = ks + ((lane >> 4) << 3);
                ldm_x4(af[0], af[1], af[2], af[3],
                       smem_u32(As + row * AROW + col));
            }
            #pragma unroll
            for (int pr = 0; pr < 6; pr++) {
                int row = pr * 16 + (lane & 7) + ((lane >> 4) << 3);
                int col = ks + (((lane >> 3) & 1) << 3);
                uint32_t b0, b1, b2, b3;
                ldm_x4(b0, b1, b2, b3, smem_u32(W1b + row * AROW + col));
                uint32_t bf0[2] = { b0, b1 };
                uint32_t bf1[2] = { b2, b3 };
                mma_bf16(facc[pr*2  ], af, bf0);
                mma_bf16(facc[pr*2+1], af, bf1);
            }
        }

        // ---- GELU + repack C-frags as FC2 A-frags (in registers) ----
        uint32_t ap[6][4];
        #pragma unroll
        for (int kt = 0; kt < 6; kt++) {
            #pragma unroll
            for (int h = 0; h < 2; h++) {
                const int nt = 2 * kt + h;
                const int col = nc * 96 + nt * 8 + tig * 2;
                const float b0 = fc1b[col], b1v = fc1b[col + 1];
                float v00 = gelu_f(facc[nt][0] + b0);
                float v01 = gelu_f(facc[nt][1] + b1v);
                float v10 = gelu_f(facc[nt][2] + b0);
                float v11 = gelu_f(facc[nt][3] + b1v);
                __nv_bfloat162 h01(__float2bfloat16(v00), __float2bfloat16(v01));
                __nv_bfloat162 h23(__float2bfloat16(v10), __float2bfloat16(v11));
                ap[kt][h * 2]     = *(uint32_t*)&h01;
                ap[kt][h * 2 + 1] = *(uint32_t*)&h23;
            }
        }

        // ---- FC2 chunk: oacc += H(16x96) @ W2[nc]^T ----
        #pragma unroll
        for (int kt = 0; kt < 6; kt++) {
            const int ks = kt * 16;
            #pragma unroll
            for (int pr = 0; pr < 6; pr++) {
                int row = pr * 16 + (lane & 7) + ((lane >> 4) << 3);
                int col = ks + (((lane >> 3) & 1) << 3);
                uint32_t b0, b1, b2, b3;
                ldm_x4(b0, b1, b2, b3, smem_u32(W2b + row * AROW + col));
                uint32_t bf0[2] = { b0, b1 };
                uint32_t bf1[2] = { b2, b3 };
                mma_bf16(oacc[pr*2  ], ap[kt], bf0);
                mma_bf16(oacc[pr*2+1], ap[kt], bf1);
            }
        }
        __syncthreads();   // all reads of this chunk's buffers done

        if (nc == 0) { issueW2(1, 0); issueW1(2, 1); }
        else if (nc == 1) { issueW2(2, 2); issueW1(3, 0); }
        else if (nc == 2) { issueW2(3, 1); }
    }

    // ---- epilogue: bias + x1 residual -> out (fp32) ----
    const int r0 = bm + warp * 16 + gid;
    const int r1 = r0 + 8;
    #pragma unroll
    for (int nt = 0; nt < 12; nt++) {
        const int col = nt * 8 + tig * 2;
        const float b0 = fc2b[col], b1v = fc2b[col + 1];
        float2 x0 = *(const float2*)&x1[(size_t)r0 * CDIM + col];
        float2 x1v = *(const float2*)&x1[(size_t)r1 * CDIM + col];
        *(float2*)&out[(size_t)r0 * CDIM + col] =
            make_float2(oacc[nt][0] + b0 + x0.x,
                        oacc[nt][1] + b1v + x0.y);
        *(float2*)&out[(size_t)r1 * CDIM + col] =
            make_float2(oacc[nt][2] + b0 + x1v.x,
                        oacc[nt][3] + b1v + x1v.y);
    }
}

// ---------------- tensor-core windowed attention (R15 version) --------------
#define ATTN_SMEM 37888

__global__ void __launch_bounds__(256)
attn_tc(const bf16* __restrict__ qkv, bf16* __restrict__ o)
{
    extern __shared__ __align__(16) char sm_[];
    bf16 (*S)[296] = (bf16(*)[296])sm_;

    const int win  = blockIdx.x;
    const int t    = threadIdx.x;
    const int warp = t >> 5, lane = t & 31;
    const int head = warp >> 1, mh = warp & 1;
    const int gid  = lane >> 2, tig = lane & 3;

    const bf16* wq = qkv + (size_t)win * 64 * C3;

    #pragma unroll
    for (int i = 0; i < 9; i++) {
        int cid = t + i * 256;
        int row = cid / 36, c = cid % 36;
        cp16(smem_u32(&S[row][c * 8]), wq + (size_t)row * C3 + c * 8);
    }
    cp_commit();
    cp_wait0();
    __syncthreads();

    const int qc = head * HD;
    const int kc = 96 + head * HD;
    const int vc = 192 + head * HD;

    uint32_t aq[2][2][4];
    #pragma unroll
    for (int mt = 0; mt < 2; mt++) {
        #pragma unroll
        for (int kt = 0; kt < 2; kt++) {
            int row = mh * 32 + mt * 16 + (lane & 15);
            int col = qc + kt * 16 + ((lane >> 4) << 3);
            ldm_x4(aq[mt][kt][0], aq[mt][kt][1], aq[mt][kt][2], aq[mt][kt][3],
                   smem_u32(&S[row][col]));
        }
        aq[mt][1][2] = 0u; aq[mt][1][3] = 0u;
    }
    uint32_t bk[8][2][2];
    #pragma unroll
    for (int np = 0; np < 4; np++) {
        #pragma unroll
        for (int kt = 0; kt < 2; kt++) {
            int row = np * 16 + (lane & 7) + ((lane >> 4) << 3);
            int col = kc + kt * 16 + (((lane >> 3) & 1) << 3);
            uint32_t r0, r1, r2, r3;
            ldm_x4(r0, r1, r2, r3, smem_u32(&S[row][col]));
            bk[np*2  ][kt][0] = r0; bk[np*2  ][kt][1] = (kt == 0) ? r1 : 0u;
            bk[np*2+1][kt][0] = r2; bk[np*2+1][kt][1] = (kt == 0) ? r3 : 0u;
        }
    }

    float acc[2][8][4];
    #pragma unroll
    for (int mt = 0; mt < 2; mt++)
        #pragma unroll
        for (int nt = 0; nt < 8; nt++)
            #pragma unroll
            for (int q = 0; q < 4; q++) acc[mt][nt][q] = 0.0f;

    #pragma unroll
    for (int mt = 0; mt < 2; mt++)
        #pragma unroll
        for (int nt = 0; nt < 8; nt++)
            #pragma unroll
            for (int kt = 0; kt < 2; kt++)
                mma_bf16(acc[mt][nt], aq[mt][kt], bk[nt][kt]);

    const int wimg = win & 63;
    const int cls = (((wimg >> 3) == 7) ? 2 : 0) | (((wimg & 7) == 7) ? 1 : 0);
    const float* bt = g_bias_exp + cls * 16384;

    const float K1 = 0.2944888985f;

    uint32_t p01[2][8], p23[2][8];
    float rs0[2] = {0.f, 0.f}, rs1[2] = {0.f, 0.f};
    #pragma unroll
    for (int mt = 0; mt < 2; mt++) {
        #pragma unroll
        for (int nt = 0; nt < 8; nt++) {
            const float4 bb = *(const float4*)&bt[
                (((((head * 2 + mh) * 2 + mt) * 8 + nt) * 32 + lane) << 2)];
            float e00 = exp2_poly(acc[mt][nt][0] * K1 + bb.x);
            float e01 = exp2_poly(acc[mt][nt][1] * K1 + bb.y);
            float e10 = exp2_poly(acc[mt][nt][2] * K1 + bb.z);
            float e11 = exp2_poly(acc[mt][nt][3] * K1 + bb.w);
            rs0[mt] += e00 + e01;
            rs1[mt] += e10 + e11;
            __nv_bfloat162 h01(__float2bfloat16(e00), __float2bfloat16(e01));
            __nv_bfloat162 h23(__float2bfloat16(e10), __float2bfloat16(e11));
            p01[mt][nt] = *(uint32_t*)&h01;
            p23[mt][nt] = *(uint32_t*)&h23;
        }
    }
    #pragma unroll
    for (int mt = 0; mt < 2; mt++) {
        #pragma unroll
        for (int o = 1; o <= 2; o <<= 1) {
            rs0[mt] += __shfl_xor_sync(0xffffffffu, rs0[mt], o);
            rs1[mt] += __shfl_xor_sync(0xffffffffu, rs1[mt], o);
        }
    }

    float ao[2][3][4];
    #pragma unroll
    for (int mt = 0; mt < 2; mt++)
        #pragma unroll
        for (int nv = 0; nv < 3; nv++)
            #pragma unroll
            for (int q = 0; q < 4; q++) ao[mt][nv][q] = 0.0f;

    #pragma unroll
    for (int kt = 0; kt < 4; kt++) {
        int row = kt * 16 + (lane & 7) + (((lane >> 3) & 1) << 3);
        uint32_t bv[3][2];
        {
            uint32_t r0, r1, r2, r3;
            int col = vc + ((lane >> 4) << 3);
            ldm_x4_t(r0, r1, r2, r3, smem_u32(&S[row][col]));
            bv[0][0] = r0; bv[0][1] = r1;
            bv[1][0] = r2; bv[1][1] = r3;
        }
        {
            uint32_t r0, r1, r2, r3;
            int col = vc + 16 + ((lane >> 4) << 3);
            ldm_x4_t(r0, r1, r2, r3, smem_u32(&S[row][col]));
            bv[2][0] = r0; bv[2][1] = r1;
        }
        #pragma unroll
        for (int mt = 0; mt < 2; mt++) {
            uint32_t ap[4] = { p01[mt][2*kt], p23[mt][2*kt],
                               p01[mt][2*kt+1], p23[mt][2*kt+1] };
            #pragma unroll
            for (int nv = 0; nv < 3; nv++)
                mma_bf16(ao[mt][nv], ap, bv[nv]);
        }
    }

    #pragma unroll
    for (int mt = 0; mt < 2; mt++) {
        float inv0 = __fdividef(1.0f, rs0[mt]);
        float inv1 = __fdividef(1.0f, rs1[mt]);
        int row0 = win * 64 + mh * 32 + mt * 16 + gid;
        #pragma unroll
        for (int nv = 0; nv < 3; nv++) {
            int col = head * HD + nv * 8 + tig * 2;
            *(__nv_bfloat162*)&o[(size_t)row0 * CDIM + col] =
                __nv_bfloat162(__float2bfloat16(ao[mt][nv][0] * inv0),
                               __float2bfloat16(ao[mt][nv][1] * inv0));
            *(__nv_bfloat162*)&o[(size_t)(row0 + 8) * CDIM + col] =
                __nv_bfloat162(__float2bfloat16(ao[mt][nv][2] * inv1),
                               __float2bfloat16(ao[mt][nv][3] * inv1));
        }
    }
}

// ---------------- launch ----------------------------------------------------
extern "C" void kernel_launch(void* const* d_in, const int* in_sizes, int n_in,
                              void* d_out, int out_size)
{
    const float* x       = (const float*)d_in[0];
    const float* norm1_g = (const float*)d_in[1];
    const float* norm1_b = (const float*)d_in[2];
    const float* qkv_w   = (const float*)d_in[3];
    const float* qkv_b   = (const float*)d_in[4];
    const float* rpb     = (const float*)d_in[5];
    const float* proj_w  = (const float*)d_in[6];
    const float* proj_b  = (const float*)d_in[7];
    const float* norm2_g = (const float*)d_in[8];
    const float* norm2_b = (const float*)d_in[9];
    const float* fc1_w   = (const float*)d_in[10];
    const float* fc1_b   = (const float*)d_in[11];
    const float* fc2_w   = (const float*)d_in[12];
    const float* fc2_b   = (const float*)d_in[13];
    float* out = (float*)d_out;

    bf16 *qkv_p, *o_p, *h2_p;
    bf16 *wqkv_p, *wproj_p;
    float *x1_p;
    cudaGetSymbolAddress((void**)&qkv_p,  g_qkv);
    cudaGetSymbolAddress((void**)&o_p,    g_o);
    cudaGetSymbolAddress((void**)&x1_p,   g_x1);
    cudaGetSymbolAddress((void**)&h2_p,   g_h2);
    cudaGetSymbolAddress((void**)&wqkv_p, g_wqkv);
    cudaGetSymbolAddress((void**)&wproj_p,g_wproj);

    cudaFuncSetAttribute(attn_tc, cudaFuncAttributeMaxDynamicSharedMemorySize,
                         ATTN_SMEM);
    cudaFuncSetAttribute(qkv_nloop,
                         cudaFuncAttributeMaxDynamicSharedMemorySize, NLOOP_SMEM);
    cudaFuncSetAttribute(mlp_fused,
                         cudaFuncAttributeMaxDynamicSharedMemorySize, MLP_SMEM);

    conv_weights<<<(CH*CDIM + 255)/256, 256>>>(qkv_w, proj_w, fc1_w, fc2_w);
    build_bias<<<256, 256>>>(rpb);

    // LN1 + shift/window + QKV
    qkv_nloop<<<TOKENS/128, 256, NLOOP_SMEM>>>(
        x, wqkv_p, qkv_b, norm1_g, norm1_b, qkv_p);

    // windowed attention
    attn_tc<<<NWIN, 256, ATTN_SMEM>>>(qkv_p, o_p);

    // proj + window-reverse + residual + LN2 -> x1 (fp32), h2 (bf16)
    proj_ln2<<<TOKENS/128, 256>>>(o_p, wproj_p, proj_b, x,
                                  norm2_g, norm2_b, x1_p, h2_p);

    // fused FC1 + GELU + FC2 + residual -> out (H in registers)
    mlp_fused<<<TOKENS/128, 256, MLP_SMEM>>>(h2_p, fc1_b, fc2_b, x1_p, out);
}

// round 17
// speedup vs baseline: 1.1655x; 1.0409x over previous
#include <cuda_runtime.h>
#include <cuda_bf16.h>
#include <cuda_fp16.h>
#include <cstdint>
#include <cstddef>

// ---------------- static problem sizes -------------------------------------
#define SS      4
#define NH      4
#define CDIM    96
#define HD      24
#define NWIN    4096
#define TOKENS  262144
#define C3      288
#define CH      384

typedef __nv_bfloat16 bf16;

// ---------------- scratch ---------------------------------------------------
__device__ bf16  g_qkv[(size_t)TOKENS * C3];
__device__ float g_x1 [(size_t)TOKENS * CDIM];
__device__ bf16  g_h2 [(size_t)TOKENS * CDIM];
__device__ bf16  g_wqkv[C3 * CDIM];
__device__ bf16  g_wproj[CDIM * CDIM];
__device__ bf16  g_wfc1[CH * CDIM];
__device__ bf16  g_wfc2[CDIM * CH];
__device__ float g_bias_exp[4 * 16384];

// ---------------- asm helpers ----------------------------------------------
__device__ __forceinline__ uint32_t smem_u32(const void* p) {
    return (uint32_t)__cvta_generic_to_shared(p);
}
__device__ __forceinline__ void ldm_x4(uint32_t& r0, uint32_t& r1, uint32_t& r2,
                                       uint32_t& r3, uint32_t addr) {
    asm volatile("ldmatrix.sync.aligned.m8n8.x4.shared.b16 {%0,%1,%2,%3}, [%4];\n"
                 : "=r"(r0), "=r"(r1), "=r"(r2), "=r"(r3) : "r"(addr));
}
__device__ __forceinline__ void ldm_x4_t(uint32_t& r0, uint32_t& r1, uint32_t& r2,
                                         uint32_t& r3, uint32_t addr) {
    asm volatile("ldmatrix.sync.aligned.m8n8.x4.trans.shared.b16 {%0,%1,%2,%3}, [%4];\n"
                 : "=r"(r0), "=r"(r1), "=r"(r2), "=r"(r3) : "r"(addr));
}
__device__ __forceinline__ void mma_bf16(float c[4], const uint32_t a[4],
                                         const uint32_t b[2]) {
    asm volatile(
        "mma.sync.aligned.m16n8k16.row.col.f32.bf16.bf16.f32 "
        "{%0,%1,%2,%3},{%4,%5,%6,%7},{%8,%9},{%0,%1,%2,%3};\n"
        : "+f"(c[0]), "+f"(c[1]), "+f"(c[2]), "+f"(c[3])
        : "r"(a[0]), "r"(a[1]), "r"(a[2]), "r"(a[3]), "r"(b[0]), "r"(b[1]));
}
__device__ __forceinline__ void cp16(uint32_t dst, const void* src) {
    asm volatile("cp.async.ca.shared.global [%0], [%1], 16;\n"
                 :: "r"(dst), "l"(src));
}
__device__ __forceinline__ void cp_commit() { asm volatile("cp.async.commit_group;\n"); }
__device__ __forceinline__ void cp_wait0() { asm volatile("cp.async.wait_group 0;\n"); }
__device__ __forceinline__ void cp_wait1() { asm volatile("cp.async.wait_group 1;\n"); }
template<int N>
__device__ __forceinline__ void cp_waitN() {
    asm volatile("cp.async.wait_group %0;\n" :: "n"(N));
}

__device__ __forceinline__ float exp2_poly(float z) {
    z = fmaxf(z, -100.0f);
    float t = z + 12582912.0f;
    int   n = __float_as_int(t) - 0x4B400000;
    float f = z - (t - 12582912.0f);
    float p = 0.009618129107f;
    p = p * f + 0.05550410866f;
    p = p * f + 0.2402265069f;
    p = p * f + 0.69314718056f;
    p = p * f + 1.0f;
    return p * __int_as_float((n + 127) << 23);
}
__device__ __forceinline__ float gelu_f(float v) {
    return 0.5f * v * (1.0f + erff(v * 0.70710678118654752f));
}

// ---------------- weight conversion -----------------------------------------
__global__ void conv_weights(const float* __restrict__ a, const float* __restrict__ b,
                             const float* __restrict__ c, const float* __restrict__ d)
{
    int i = blockIdx.x * 256 + threadIdx.x;
    if (i < C3 * CDIM)   g_wqkv[i]  = __float2bfloat16(a[i]);
    if (i < CDIM * CDIM) g_wproj[i] = __float2bfloat16(b[i]);
    if (i < CH * CDIM) { g_wfc1[i]  = __float2bfloat16(c[i]);
                         g_wfc2[i]  = __float2bfloat16(d[i]); }
}

// ---------------- bias+mask expansion (4 window classes) --------------------
__global__ void build_bias(const float* __restrict__ rpb)
{
    int idx = blockIdx.x * 256 + threadIdx.x;
    int cls = idx >> 14;
    int e   = idx & 16383;
    int q    = e & 3;
    int lane = (e >> 2) & 31;
    int nt   = (e >> 7) & 7;
    int mt   = (e >> 10) & 1;
    int mh   = (e >> 11) & 1;
    int head = (e >> 12) & 3;
    int gid = lane >> 2, tig = lane & 3;
    int n = mh*32 + mt*16 + gid + ((q >> 1) << 3);
    int m = nt*8 + tig*2 + (q & 1);
    int ni = n >> 3, nj = n & 7, mi = m >> 3, mj = m & 7;
    int ridx = (ni - mi + 7) * 15 + (nj - mj + 7);
    int wi7 = cls >> 1, wj7 = cls & 1;
    int rq = (wi7 ? ((ni < 4) ? 1 : 2) : 0) * 3 + (wj7 ? ((nj < 4) ? 1 : 2) : 0);
    int rk = (wi7 ? ((mi < 4) ? 1 : 2) : 0) * 3 + (wj7 ? ((mj < 4) ? 1 : 2) : 0);
    float mask = (rq != rk) ? -144.269504089f : 0.0f;
    g_bias_exp[idx] = rpb[ridx * NH + head] * 1.4426950408889634f + mask;
}

// ---------------- vectorized LN row helper ----------------------------------
__device__ __forceinline__ void ln_row_v4(const float* __restrict__ xr,
                                          const float* __restrict__ g,
                                          const float* __restrict__ b,
                                          bf16* __restrict__ orow, int lane)
{
    float4 v = make_float4(0.f, 0.f, 0.f, 0.f);
    if (lane < 24) v = *(const float4*)(xr + lane * 4);
    float s  = v.x + v.y + v.z + v.w;
    float ss = v.x*v.x + v.y*v.y + v.z*v.z + v.w*v.w;
    #pragma unroll
    for (int o = 16; o; o >>= 1) {
        s  += __shfl_xor_sync(0xffffffffu, s,  o);
        ss += __shfl_xor_sync(0xffffffffu, ss, o);
    }
    float mu = s * (1.0f/CDIM);
    float rs = rsqrtf(ss * (1.0f/CDIM) - mu*mu + 1e-5f);
    if (lane < 24) {
        float4 gv = *(const float4*)(g + lane * 4);
        float4 bv = *(const float4*)(b + lane * 4);
        __nv_bfloat162 lo((__nv_bfloat16)((v.x - mu) * rs * gv.x + bv.x),
                          (__nv_bfloat16)((v.y - mu) * rs * gv.y + bv.y));
        __nv_bfloat162 hi((__nv_bfloat16)((v.z - mu) * rs * gv.z + bv.z),
                          (__nv_bfloat16)((v.w - mu) * rs * gv.w + bv.w));
        uint2 pk;
        pk.x = *(uint32_t*)&lo;
        pk.y = *(uint32_t*)&hi;
        *(uint2*)(orow + lane * 4) = pk;
    }
}

// ---------------- QKV: LN1 + shift/window + N-loop GEMM ---------------------
#define AROW 104
#define NLOOP_SMEM (128*AROW*2 + 2*96*AROW*2)

__global__ void __launch_bounds__(256, 3)
qkv_nloop(const float* __restrict__ x, const bf16* __restrict__ W,
          const float* __restrict__ bias,
          const float* __restrict__ g1, const float* __restrict__ b1,
          bf16* __restrict__ Cout)
{
    extern __shared__ __align__(16) char dyn[];
    bf16* As = (bf16*)dyn;
    bf16* Bs = (bf16*)(dyn + 128*AROW*2);

    const int t = threadIdx.x, warp = t >> 5, lane = t & 31;
    const int bm = blockIdx.x * 128;
    const int wrow = warp & 3, wcol = warp >> 2;
    const int gid = lane >> 2, tig = lane & 3;

    auto issueB = [&](int nc, int buf) {
        const bf16* Wb = W + (size_t)(nc * 96) * CDIM;
        bf16* Bd = Bs + buf * 96 * AROW;
        #pragma unroll
        for (int cid = t; cid < 1152; cid += 256) {
            int row = cid / 12, c = cid % 12;
            cp16(smem_u32(Bd + row * AROW + c * 8),
                 Wb + (size_t)row * CDIM + c * 8);
        }
        cp_commit();
    };

    issueB(0, 0);

    #pragma unroll
    for (int it = 0; it < 16; it++) {
        int r  = it * 8 + warp;
        int wr = bm + r;
        int w = (wr >> 6) & 63, s = wr & 63;
        int i0 = ((w >> 3) << 3) + (s >> 3), j0 = ((w & 7) << 3) + (s & 7);
        int src = (wr & ~4095) | ((((i0 + SS) & 63) << 6) | ((j0 + SS) & 63));
        ln_row_v4(x + (size_t)src * CDIM, g1, b1, As + r * AROW, lane);
    }

    #pragma unroll
    for (int nc = 0; nc < 3; nc++) {
        if (nc + 1 < 3) { issueB(nc + 1, (nc + 1) & 1); cp_wait1(); }
        else            { cp_wait0(); }
        __syncthreads();
        const bf16* Bb = Bs + (nc & 1) * 96 * AROW;

        float acc[2][6][4];
        #pragma unroll
        for (int i = 0; i < 2; i++)
            #pragma unroll
            for (int j = 0; j < 6; j++)
                #pragma unroll
                for (int q = 0; q < 4; q++) acc[i][j][q] = 0.0f;

        #pragma unroll
        for (int ks = 0; ks < 96; ks += 16) {
            uint32_t af[2][4];
            #pragma unroll
            for (int mt = 0; mt < 2; mt++) {
                int row = wrow * 32 + mt * 16 + (lane & 15);
                int col = ks + ((lane >> 4) << 3);
                ldm_x4(af[mt][0], af[mt][1], af[mt][2], af[mt][3],
                       smem_u32(As + row * AROW + col));
            }
            uint32_t bfm[6][2];
            #pragma unroll
            for (int pr = 0; pr < 3; pr++) {
                int row = wcol * 48 + pr * 16 + (lane & 7) + ((lane >> 4) << 3);
                int col = ks + (((lane >> 3) & 1) << 3);
                uint32_t r0, r1, r2, r3;
                ldm_x4(r0, r1, r2, r3, smem_u32(Bb + row * AROW + col));
                bfm[pr*2  ][0] = r0; bfm[pr*2  ][1] = r1;
                bfm[pr*2+1][0] = r2; bfm[pr*2+1][1] = r3;
            }
            #pragma unroll
            for (int mt = 0; mt < 2; mt++)
                #pragma unroll
                for (int nt = 0; nt < 6; nt++)
                    mma_bf16(acc[mt][nt], af[mt], bfm[nt]);
        }

        #pragma unroll
        for (int mt = 0; mt < 2; mt++) {
            const int r0 = bm + wrow * 32 + mt * 16 + gid;
            const int r1 = r0 + 8;
            #pragma unroll
            for (int nt = 0; nt < 6; nt++) {
                const int col = nc * 96 + wcol * 48 + nt * 8 + tig * 2;
                const float b0 = bias[col], b1v = bias[col + 1];
                *(__nv_bfloat162*)&Cout[(size_t)r0 * C3 + col] =
                    __nv_bfloat162(__float2bfloat16(acc[mt][nt][0] + b0),
                                   __float2bfloat16(acc[mt][nt][1] + b1v));
                *(__nv_bfloat162*)&Cout[(size_t)r1 * C3 + col] =
                    __nv_bfloat162(__float2bfloat16(acc[mt][nt][2] + b0),
                                   __float2bfloat16(acc[mt][nt][3] + b1v));
            }
        }
        __syncthreads();
    }
}

// ---------------- fused MLP: FC1+GELU (registers) -> FC2 + residual ---------
#define MLP_SMEM (26624 + 3*96*AROW*2)

__global__ void __launch_bounds__(256, 2)
mlp_fused(const bf16* __restrict__ h2, const float* __restrict__ fc1b,
          const float* __restrict__ fc2b, const float* __restrict__ x1,
          float* __restrict__ out)
{
    extern __shared__ __align__(16) char dyn[];
    bf16* As = (bf16*)dyn;
    bf16* Wb = (bf16*)(dyn + 26624);

    const int t = threadIdx.x, warp = t >> 5, lane = t & 31;
    const int bm = blockIdx.x * 128;
    const int gid = lane >> 2, tig = lane & 3;

    auto issueW1 = [&](int nc, int buf) {
        const bf16* src = g_wfc1 + (size_t)(nc * 96) * CDIM;
        bf16* Bd = Wb + buf * 96 * AROW;
        #pragma unroll
        for (int cid = t; cid < 1152; cid += 256) {
            int row = cid / 12, c = cid % 12;
            cp16(smem_u32(Bd + row * AROW + c * 8),
                 src + (size_t)row * CDIM + c * 8);
        }
        cp_commit();
    };
    auto issueW2 = [&](int nc, int buf) {
        const bf16* src = g_wfc2 + nc * 96;
        bf16* Bd = Wb + buf * 96 * AROW;
        #pragma unroll
        for (int cid = t; cid < 1152; cid += 256) {
            int row = cid / 12, c = cid % 12;
            cp16(smem_u32(Bd + row * AROW + c * 8),
                 src + (size_t)row * CH + c * 8);
        }
        cp_commit();
    };

    {
        #pragma unroll
        for (int cid = t; cid < 1536; cid += 256) {
            int row = cid / 12, c = cid % 12;
            cp16(smem_u32(As + row * AROW + c * 8),
                 h2 + (size_t)(bm + row) * CDIM + c * 8);
        }
        const bf16* src = g_wfc1;
        #pragma unroll
        for (int cid = t; cid < 1152; cid += 256) {
            int row = cid / 12, c = cid % 12;
            cp16(smem_u32(Wb + row * AROW + c * 8),
                 src + (size_t)row * CDIM + c * 8);
        }
        cp_commit();
    }
    issueW2(0, 1);
    issueW1(1, 2);

    float oacc[12][4];
    #pragma unroll
    for (int j = 0; j < 12; j++)
        #pragma unroll
        for (int q = 0; q < 4; q++) oacc[j][q] = 0.0f;

    #pragma unroll
    for (int nc = 0; nc < 4; nc++) {
        if (nc == 3) cp_waitN<0>(); else cp_waitN<1>();
        __syncthreads();
        const bf16* W1b = Wb + ((2 * nc) % 3) * 96 * AROW;
        const bf16* W2b = Wb + ((2 * nc + 1) % 3) * 96 * AROW;

        float facc[12][4];
        #pragma unroll
        for (int j = 0; j < 12; j++)
            #pragma unroll
            for (int q = 0; q < 4; q++) facc[j][q] = 0.0f;

        #pragma unroll
        for (int ks = 0; ks < 96; ks += 16) {
            uint32_t af[4];
            {
                int row = warp * 16 + (lane & 15);
                int col = ks + ((lane >> 4) << 3);
                ldm_x4(af[0], af[1], af[2], af[3],
                       smem_u32(As + row * AROW + col));
            }
            #pragma unroll
            for (int pr = 0; pr < 6; pr++) {
                int row = pr * 16 + (lane & 7) + ((lane >> 4) << 3);
                int col = ks + (((lane >> 3) & 1) << 3);
                uint32_t b0, b1, b2, b3;
                ldm_x4(b0, b1, b2, b3, smem_u32(W1b + row * AROW + col));
                uint32_t bf0[2] = { b0, b1 };
                uint32_t bf1[2] = { b2, b3 };
                mma_bf16(facc[pr*2  ], af, bf0);
                mma_bf16(facc[pr*2+1], af, bf1);
            }
        }

        uint32_t ap[6][4];
        #pragma unroll
        for (int kt = 0; kt < 6; kt++) {
            #pragma unroll
            for (int h = 0; h < 2; h++) {
                const int nt = 2 * kt + h;
                const int col = nc * 96 + nt * 8 + tig * 2;
                const float b0 = fc1b[col], b1v = fc1b[col + 1];
                float v00 = gelu_f(facc[nt][0] + b0);
                float v01 = gelu_f(facc[nt][1] + b1v);
                float v10 = gelu_f(facc[nt][2] + b0);
                float v11 = gelu_f(facc[nt][3] + b1v);
                __nv_bfloat162 h01(__float2bfloat16(v00), __float2bfloat16(v01));
                __nv_bfloat162 h23(__float2bfloat16(v10), __float2bfloat16(v11));
                ap[kt][h * 2]     = *(uint32_t*)&h01;
                ap[kt][h * 2 + 1] = *(uint32_t*)&h23;
            }
        }

        #pragma unroll
        for (int kt = 0; kt < 6; kt++) {
            const int ks = kt * 16;
            #pragma unroll
            for (int pr = 0; pr < 6; pr++) {
                int row = pr * 16 + (lane & 7) + ((lane >> 4) << 3);
                int col = ks + (((lane >> 3) & 1) << 3);
                uint32_t b0, b1, b2, b3;
                ldm_x4(b0, b1, b2, b3, smem_u32(W2b + row * AROW + col));
                uint32_t bf0[2] = { b0, b1 };
                uint32_t bf1[2] = { b2, b3 };
                mma_bf16(oacc[pr*2  ], ap[kt], bf0);
                mma_bf16(oacc[pr*2+1], ap[kt], bf1);
            }
        }
        __syncthreads();

        if (nc == 0) { issueW2(1, 0); issueW1(2, 1); }
        else if (nc == 1) { issueW2(2, 2); issueW1(3, 0); }
        else if (nc == 2) { issueW2(3, 1); }
    }

    const int r0 = bm + warp * 16 + gid;
    const int r1 = r0 + 8;
    #pragma unroll
    for (int nt = 0; nt < 12; nt++) {
        const int col = nt * 8 + tig * 2;
        const float b0 = fc2b[col], b1v = fc2b[col + 1];
        float2 x0 = *(const float2*)&x1[(size_t)r0 * CDIM + col];
        float2 x1v = *(const float2*)&x1[(size_t)r1 * CDIM + col];
        *(float2*)&out[(size_t)r0 * CDIM + col] =
            make_float2(oacc[nt][0] + b0 + x0.x,
                        oacc[nt][1] + b1v + x0.y);
        *(float2*)&out[(size_t)r1 * CDIM + col] =
            make_float2(oacc[nt][2] + b0 + x1v.x,
                        oacc[nt][3] + b1v + x1v.y);
    }
}

// ---------------- fused attention + proj + residual + LN2 -------------------
// dyn smem: S[64][296] (37888) + Wp[96][104] (19968) + Ot[64][104] (13312)
#define AP_SMEM (37888 + 19968 + 13312)

__global__ void __launch_bounds__(256, 2)
attn_proj(const bf16* __restrict__ qkv, const bf16* __restrict__ Wp_g,
          const float* __restrict__ pbias, const float* __restrict__ xres,
          const float* __restrict__ g2, const float* __restrict__ b2,
          float* __restrict__ X1, bf16* __restrict__ H2)
{
    extern __shared__ __align__(16) char sm_[];
    bf16 (*S)[296]  = (bf16(*)[296])sm_;
    bf16* Wp = (bf16*)(sm_ + 37888);
    bf16* Ot = (bf16*)(sm_ + 37888 + 19968);
    __shared__ float red_s[64][2];
    __shared__ float red_ss[64][2];

    const int win  = blockIdx.x;
    const int t    = threadIdx.x;
    const int warp = t >> 5, lane = t & 31;
    const int head = warp >> 1, mh = warp & 1;
    const int gid  = lane >> 2, tig = lane & 3;

    const bf16* wq = qkv + (size_t)win * 64 * C3;

    // ---- stage QKV tile + W_proj ----
    #pragma unroll
    for (int i = 0; i < 9; i++) {
        int cid = t + i * 256;
        int row = cid / 36, c = cid % 36;
        cp16(smem_u32(&S[row][c * 8]), wq + (size_t)row * C3 + c * 8);
    }
    #pragma unroll
    for (int cid = t; cid < 1152; cid += 256) {
        int row = cid / 12, c = cid % 12;
        cp16(smem_u32(Wp + row * AROW + c * 8),
             Wp_g + (size_t)row * CDIM + c * 8);
    }
    cp_commit();
    cp_wait0();
    __syncthreads();

    const int qc = head * HD;
    const int kc = 96 + head * HD;
    const int vc = 192 + head * HD;

    // ---- Q/K fragments ----
    uint32_t aq[2][2][4];
    #pragma unroll
    for (int mt = 0; mt < 2; mt++) {
        #pragma unroll
        for (int kt = 0; kt < 2; kt++) {
            int row = mh * 32 + mt * 16 + (lane & 15);
            int col = qc + kt * 16 + ((lane >> 4) << 3);
            ldm_x4(aq[mt][kt][0], aq[mt][kt][1], aq[mt][kt][2], aq[mt][kt][3],
                   smem_u32(&S[row][col]));
        }
        aq[mt][1][2] = 0u; aq[mt][1][3] = 0u;
    }
    uint32_t bk[8][2][2];
    #pragma unroll
    for (int np = 0; np < 4; np++) {
        #pragma unroll
        for (int kt = 0; kt < 2; kt++) {
            int row = np * 16 + (lane & 7) + ((lane >> 4) << 3);
            int col = kc + kt * 16 + (((lane >> 3) & 1) << 3);
            uint32_t r0, r1, r2, r3;
            ldm_x4(r0, r1, r2, r3, smem_u32(&S[row][col]));
            bk[np*2  ][kt][0] = r0; bk[np*2  ][kt][1] = (kt == 0) ? r1 : 0u;
            bk[np*2+1][kt][0] = r2; bk[np*2+1][kt][1] = (kt == 0) ? r3 : 0u;
        }
    }

    // ---- S = Q @ K^T ----
    float acc[2][8][4];
    #pragma unroll
    for (int mt = 0; mt < 2; mt++)
        #pragma unroll
        for (int nt = 0; nt < 8; nt++)
            #pragma unroll
            for (int q = 0; q < 4; q++) acc[mt][nt][q] = 0.0f;

    #pragma unroll
    for (int mt = 0; mt < 2; mt++)
        #pragma unroll
        for (int nt = 0; nt < 8; nt++)
            #pragma unroll
            for (int kt = 0; kt < 2; kt++)
                mma_bf16(acc[mt][nt], aq[mt][kt], bk[nt][kt]);

    const int wimg = win & 63;
    const int cls = (((wimg >> 3) == 7) ? 2 : 0) | (((wimg & 7) == 7) ? 1 : 0);
    const float* bt = g_bias_exp + cls * 16384;
    const float K1 = 0.2944888985f;

    // ---- exp + row sums; pack P ----
    uint32_t p01[2][8], p23[2][8];
    float rsum0[2] = {0.f, 0.f}, rsum1[2] = {0.f, 0.f};
    #pragma unroll
    for (int mt = 0; mt < 2; mt++) {
        #pragma unroll
        for (int nt = 0; nt < 8; nt++) {
            const float4 bb = *(const float4*)&bt[
                (((((head * 2 + mh) * 2 + mt) * 8 + nt) * 32 + lane) << 2)];
            float e00 = exp2_poly(acc[mt][nt][0] * K1 + bb.x);
            float e01 = exp2_poly(acc[mt][nt][1] * K1 + bb.y);
            float e10 = exp2_poly(acc[mt][nt][2] * K1 + bb.z);
            float e11 = exp2_poly(acc[mt][nt][3] * K1 + bb.w);
            rsum0[mt] += e00 + e01;
            rsum1[mt] += e10 + e11;
            __nv_bfloat162 h01(__float2bfloat16(e00), __float2bfloat16(e01));
            __nv_bfloat162 h23(__float2bfloat16(e10), __float2bfloat16(e11));
            p01[mt][nt] = *(uint32_t*)&h01;
            p23[mt][nt] = *(uint32_t*)&h23;
        }
    }
    #pragma unroll
    for (int mt = 0; mt < 2; mt++) {
        #pragma unroll
        for (int o = 1; o <= 2; o <<= 1) {
            rsum0[mt] += __shfl_xor_sync(0xffffffffu, rsum0[mt], o);
            rsum1[mt] += __shfl_xor_sync(0xffffffffu, rsum1[mt], o);
        }
    }

    // ---- O = P @ V -> smem Ot ----
    float ao[2][3][4];
    #pragma unroll
    for (int mt = 0; mt < 2; mt++)
        #pragma unroll
        for (int nv = 0; nv < 3; nv++)
            #pragma unroll
            for (int q = 0; q < 4; q++) ao[mt][nv][q] = 0.0f;

    #pragma unroll
    for (int kt = 0; kt < 4; kt++) {
        int row = kt * 16 + (lane & 7) + (((lane >> 3) & 1) << 3);
        uint32_t bv[3][2];
        {
            uint32_t r0, r1, r2, r3;
            int col = vc + ((lane >> 4) << 3);
            ldm_x4_t(r0, r1, r2, r3, smem_u32(&S[row][col]));
            bv[0][0] = r0; bv[0][1] = r1;
            bv[1][0] = r2; bv[1][1] = r3;
        }
        {
            uint32_t r0, r1, r2, r3;
            int col = vc + 16 + ((lane >> 4) << 3);
            ldm_x4_t(r0, r1, r2, r3, smem_u32(&S[row][col]));
            bv[2][0] = r0; bv[2][1] = r1;
        }
        #pragma unroll
        for (int mt = 0; mt < 2; mt++) {
            uint32_t ap[4] = { p01[mt][2*kt], p23[mt][2*kt],
                               p01[mt][2*kt+1], p23[mt][2*kt+1] };
            #pragma unroll
            for (int nv = 0; nv < 3; nv++)
                mma_bf16(ao[mt][nv], ap, bv[nv]);
        }
    }

    #pragma unroll
    for (int mt = 0; mt < 2; mt++) {
        float inv0 = __fdividef(1.0f, rsum0[mt]);
        float inv1 = __fdividef(1.0f, rsum1[mt]);
        int row0 = mh * 32 + mt * 16 + gid;
        #pragma unroll
        for (int nv = 0; nv < 3; nv++) {
            int col = head * HD + nv * 8 + tig * 2;
            *(__nv_bfloat162*)(Ot + row0 * AROW + col) =
                __nv_bfloat162(__float2bfloat16(ao[mt][nv][0] * inv0),
                               __float2bfloat16(ao[mt][nv][1] * inv0));
            *(__nv_bfloat162*)(Ot + (row0 + 8) * AROW + col) =
                __nv_bfloat162(__float2bfloat16(ao[mt][nv][2] * inv1),
                               __float2bfloat16(ao[mt][nv][3] * inv1));
        }
    }
    __syncthreads();

    // ---- proj GEMM: M=64, N=96, K=96.  warp tile 16 x 48 ----
    const int wrow = warp & 3, wcol = warp >> 2;
    float pacc[6][4];
    #pragma unroll
    for (int j = 0; j < 6; j++)
        #pragma unroll
        for (int q = 0; q < 4; q++) pacc[j][q] = 0.0f;

    #pragma unroll
    for (int ks = 0; ks < 96; ks += 16) {
        uint32_t af[4];
        {
            int row = wrow * 16 + (lane & 15);
            int col = ks + ((lane >> 4) << 3);
            ldm_x4(af[0], af[1], af[2], af[3], smem_u32(Ot + row * AROW + col));
        }
        #pragma unroll
        for (int pr = 0; pr < 3; pr++) {
            int row = wcol * 48 + pr * 16 + (lane & 7) + ((lane >> 4) << 3);
            int col = ks + (((lane >> 3) & 1) << 3);
            uint32_t b0, b1, b2, b3;
            ldm_x4(b0, b1, b2, b3, smem_u32(Wp + row * AROW + col));
            uint32_t bf0[2] = { b0, b1 };
            uint32_t bf1[2] = { b2, b3 };
            mma_bf16(pacc[pr*2  ], af, bf0);
            mma_bf16(pacc[pr*2+1], af, bf1);
        }
    }

    // ---- epilogue pass 1: residual + x1 (scattered) + LN partial sums ----
    const int lr0 = wrow * 16 + gid;
    const int lr1 = lr0 + 8;
    const int gr0 = win * 64 + lr0;
    const int gr1 = gr0 + 8;
    int w0 = (gr0 >> 6) & 63, s0 = gr0 & 63;
    int i0 = ((w0 >> 3) << 3) + (s0 >> 3), j0 = ((w0 & 7) << 3) + (s0 & 7);
    int d0 = (gr0 & ~4095) | ((((i0 + SS) & 63) << 6) | ((j0 + SS) & 63));
    int w1 = (gr1 >> 6) & 63, s1 = gr1 & 63;
    int i1 = ((w1 >> 3) << 3) + (s1 >> 3), j1 = ((w1 & 7) << 3) + (s1 & 7);
    int d1 = (gr1 & ~4095) | ((((i1 + SS) & 63) << 6) | ((j1 + SS) & 63));

    float sa = 0.f, ssa = 0.f, sb = 0.f, ssb = 0.f;
    #pragma unroll
    for (int nt = 0; nt < 6; nt++) {
        const int col = wcol * 48 + nt * 8 + tig * 2;
        const float b0 = pbias[col], b1v = pbias[col + 1];
        size_t o0 = (size_t)d0 * CDIM + col;
        size_t o1 = (size_t)d1 * CDIM + col;
        float2 x0 = *(const float2*)&xres[o0];
        float2 x1v = *(const float2*)&xres[o1];
        float v00 = pacc[nt][0] + b0 + x0.x;
        float v01 = pacc[nt][1] + b1v + x0.y;
        float v10 = pacc[nt][2] + b0 + x1v.x;
        float v11 = pacc[nt][3] + b1v + x1v.y;
        *(float2*)&X1[o0] = make_float2(v00, v01);
        *(float2*)&X1[o1] = make_float2(v10, v11);
        pacc[nt][0] = v00; pacc[nt][1] = v01;
        pacc[nt][2] = v10; pacc[nt][3] = v11;
        sa += v00 + v01;  ssa += v00*v00 + v01*v01;
        sb += v10 + v11;  ssb += v10*v10 + v11*v11;
    }
    #pragma unroll
    for (int o = 1; o <= 2; o <<= 1) {
        sa  += __shfl_xor_sync(0xffffffffu, sa,  o);
        ssa += __shfl_xor_sync(0xffffffffu, ssa, o);
        sb  += __shfl_xor_sync(0xffffffffu, sb,  o);
        ssb += __shfl_xor_sync(0xffffffffu, ssb, o);
    }
    if (tig == 0) {
        red_s [lr0][wcol] = sa;  red_ss[lr0][wcol] = ssa;
        red_s [lr1][wcol] = sb;  red_ss[lr1][wcol] = ssb;
    }
    __syncthreads();

    // ---- epilogue pass 2: LN2 -> h2 (scattered) ----
    {
        float mu0 = (red_s[lr0][0] + red_s[lr0][1]) * (1.0f/CDIM);
        float rsn0 = rsqrtf((red_ss[lr0][0] + red_ss[lr0][1]) * (1.0f/CDIM)
                            - mu0*mu0 + 1e-5f);
        float mu1 = (red_s[lr1][0] + red_s[lr1][1]) * (1.0f/CDIM);
        float rsn1 = rsqrtf((red_ss[lr1][0] + red_ss[lr1][1]) * (1.0f/CDIM)
                            - mu1*mu1 + 1e-5f);
        #pragma unroll
        for (int nt = 0; nt < 6; nt++) {
            const int col = wcol * 48 + nt * 8 + tig * 2;
            float gv0 = g2[col], gv1 = g2[col+1];
            float bv0 = b2[col], bv1 = b2[col+1];
            float h00 = (pacc[nt][0] - mu0) * rsn0 * gv0 + bv0;
            float h01 = (pacc[nt][1] - mu0) * rsn0 * gv1 + bv1;
            float h10 = (pacc[nt][2] - mu1) * rsn1 * gv0 + bv0;
            float h11 = (pacc[nt][3] - mu1) * rsn1 * gv1 + bv1;
            *(__nv_bfloat162*)&H2[(size_t)d0 * CDIM + col] =
                __nv_bfloat162(__float2bfloat16(h00), __float2bfloat16(h01));
            *(__nv_bfloat162*)&H2[(size_t)d1 * CDIM + col] =
                __nv_bfloat162(__float2bfloat16(h10), __float2bfloat16(h11));
        }
    }
}

// ---------------- launch ----------------------------------------------------
extern "C" void kernel_launch(void* const* d_in, const int* in_sizes, int n_in,
                              void* d_out, int out_size)
{
    const float* x       = (const float*)d_in[0];
    const float* norm1_g = (const float*)d_in[1];
    const float* norm1_b = (const float*)d_in[2];
    const float* qkv_w   = (const float*)d_in[3];
    const float* qkv_b   = (const float*)d_in[4];
    const float* rpb     = (const float*)d_in[5];
    const float* proj_w  = (const float*)d_in[6];
    const float* proj_b  = (const float*)d_in[7];
    const float* norm2_g = (const float*)d_in[8];
    const float* norm2_b = (const float*)d_in[9];
    const float* fc1_w   = (const float*)d_in[10];
    const float* fc1_b   = (const float*)d_in[11];
    const float* fc2_w   = (const float*)d_in[12];
    const float* fc2_b   = (const float*)d_in[13];
    float* out = (float*)d_out;

    bf16 *qkv_p, *h2_p;
    bf16 *wqkv_p, *wproj_p;
    float *x1_p;
    cudaGetSymbolAddress((void**)&qkv_p,  g_qkv);
    cudaGetSymbolAddress((void**)&x1_p,   g_x1);
    cudaGetSymbolAddress((void**)&h2_p,   g_h2);
    cudaGetSymbolAddress((void**)&wqkv_p, g_wqkv);
    cudaGetSymbolAddress((void**)&wproj_p,g_wproj);

    cudaFuncSetAttribute(attn_proj, cudaFuncAttributeMaxDynamicSharedMemorySize,
                         AP_SMEM);
    cudaFuncSetAttribute(qkv_nloop,
                         cudaFuncAttributeMaxDynamicSharedMemorySize, NLOOP_SMEM);
    cudaFuncSetAttribute(mlp_fused,
                         cudaFuncAttributeMaxDynamicSharedMemorySize, MLP_SMEM);

    conv_weights<<<(CH*CDIM + 255)/256, 256>>>(qkv_w, proj_w, fc1_w, fc2_w);
    build_bias<<<256, 256>>>(rpb);

    // LN1 + shift/window + QKV
    qkv_nloop<<<TOKENS/128, 256, NLOOP_SMEM>>>(
        x, wqkv_p, qkv_b, norm1_g, norm1_b, qkv_p);

    // attention + proj + window-reverse + residual + LN2
    attn_proj<<<NWIN, 256, AP_SMEM>>>(qkv_p, wproj_p, proj_b, x,
                                      norm2_g, norm2_b, x1_p, h2_p);

    // fused FC1 + GELU + FC2 + residual -> out
    mlp_fused<<<TOKENS/128, 256, MLP_SMEM>>>(h2_p, fc1_b, fc2_b, x1_p, out);
}